// round 1
// baseline (speedup 1.0000x reference)
#include <cuda_runtime.h>
#include <math.h>

// Problem dims
constexpr int kB = 4;
constexpr int kS = 4096;
constexpr int kD = 2048;
constexpr int kM = kB * kS;             // 16384 rows for all GEMMs

// Scratch (device globals: allocation-free rule). 4 x 128 MiB.
// g_k is reused as the y buffer after ewk has been computed.
__device__ float g_k[(size_t)kM * kD];
__device__ float g_e[(size_t)kM * kD];
__device__ float g_r[(size_t)kM * kD];
__device__ float g_v[(size_t)kM * kD];

enum { EPI_NONE = 0, EPI_SIGMOID = 1, EPI_EWK = 2 };

// C[M,N] = A[M,K] @ W[N,K]^T   (both operands row-major, K contiguous: "NT")
// 128x128 tile, BK=8, 256 threads, 8x8 per-thread microtile in z-pattern
// (4+4 rows/cols split by 64) so all smem traffic is conflict-free float4.
template <int EPI>
__global__ __launch_bounds__(256, 2)
void sgemm_nt(const float* __restrict__ A, const float* __restrict__ W,
              float* __restrict__ C, const float* __restrict__ aux,
              int Mm, int Nn, int Kk)
{
    __shared__ float As[8][128];
    __shared__ float Bs[8][128];

    const int tid = threadIdx.x;
    const int bm = blockIdx.y * 128;
    const int bn = blockIdx.x * 128;

    // Loader mapping: 256 threads x 1 float4 each per tile per operand.
    const int lr = tid >> 1;            // row within 128-row tile
    const int lc = (tid & 1) << 2;      // k offset 0 or 4
    const float* aptr = A + (size_t)(bm + lr) * Kk + lc;
    const float* wptr = W + (size_t)(bn + lr) * Kk + lc;

    // Compute mapping
    const int ty4 = (tid >> 4) << 2;    // m sub-offset (0..60)
    const int tx4 = (tid & 15) << 2;    // n sub-offset (0..60)

    float acc[8][8];
#pragma unroll
    for (int i = 0; i < 8; i++)
#pragma unroll
        for (int j = 0; j < 8; j++) acc[i][j] = 0.f;

    // Register prefetch of first tile
    float4 pa = *(const float4*)aptr;
    float4 pb = *(const float4*)wptr;

    for (int k0 = 0; k0 < Kk; k0 += 8) {
        As[lc + 0][lr] = pa.x; As[lc + 1][lr] = pa.y;
        As[lc + 2][lr] = pa.z; As[lc + 3][lr] = pa.w;
        Bs[lc + 0][lr] = pb.x; Bs[lc + 1][lr] = pb.y;
        Bs[lc + 2][lr] = pb.z; Bs[lc + 3][lr] = pb.w;
        __syncthreads();

        if (k0 + 8 < Kk) {              // prefetch next k-tile during compute
            pa = *(const float4*)(aptr + k0 + 8);
            pb = *(const float4*)(wptr + k0 + 8);
        }

#pragma unroll
        for (int kk = 0; kk < 8; kk++) {
            float4 a0 = *(const float4*)&As[kk][ty4];
            float4 a1 = *(const float4*)&As[kk][ty4 + 64];
            float4 b0 = *(const float4*)&Bs[kk][tx4];
            float4 b1 = *(const float4*)&Bs[kk][tx4 + 64];
            float a[8] = {a0.x, a0.y, a0.z, a0.w, a1.x, a1.y, a1.z, a1.w};
            float b[8] = {b0.x, b0.y, b0.z, b0.w, b1.x, b1.y, b1.z, b1.w};
#pragma unroll
            for (int i = 0; i < 8; i++)
#pragma unroll
                for (int j = 0; j < 8; j++)
                    acc[i][j] = fmaf(a[i], b[j], acc[i][j]);
        }
        __syncthreads();
    }

    // Epilogue (vectorized stores, optional fused nonlinearity)
#pragma unroll
    for (int i = 0; i < 8; i++) {
        const int m = bm + ty4 + (i < 4 ? i : i + 60);
#pragma unroll
        for (int h = 0; h < 2; h++) {
            const int n = bn + tx4 + h * 64;
            const size_t idx = (size_t)m * Nn + n;
            float t[4];
#pragma unroll
            for (int j = 0; j < 4; j++) {
                float vvl = acc[i][h * 4 + j];
                if (EPI == EPI_SIGMOID) {
                    vvl = 1.f / (1.f + expf(-vvl));
                } else if (EPI == EPI_EWK) {
                    // acc = x@Ww^T ; aux = k.  ewk = exp(k - exp(xWw))
                    vvl = expf(aux[idx + j] - expf(vvl));
                }
                t[j] = vvl;
            }
            float4 o = {t[0], t[1], t[2], t[3]};
            *(float4*)(C + idx) = o;
        }
    }
}

// Sequential WKV scan: one thread per (b, d) channel.
// y[b,s,d] = r * (num/(den+1e-8)) with num/den recurrences; also writes
// final_state [B,2,D] (num then den) at state_out.
__global__ void scan_kernel(const float* __restrict__ ewk,
                            const float* __restrict__ v,
                            const float* __restrict__ r,
                            const float* __restrict__ time_decay,
                            float* __restrict__ y,
                            float* __restrict__ state_out)
{
    const int idx = blockIdx.x * blockDim.x + threadIdx.x;   // 0 .. B*D-1
    const int b = idx / kD;
    const int d = idx - b * kD;
    const float decay = expf(time_decay[d]);

    float num = 0.f, den = 0.f;
    size_t base = (size_t)b * kS * kD + d;
    for (int s = 0; s < kS; s++) {
        const size_t i = base + (size_t)s * kD;
        const float e = ewk[i];
        const float vv = v[i];
        const float rr = r[i];
        num = decay * num + e * vv;
        den = decay * den + e;
        y[i] = rr * (num / (den + 1e-8f));
    }
    state_out[(size_t)b * 2 * kD + d] = num;         // num
    state_out[(size_t)b * 2 * kD + kD + d] = den;    // den
}

extern "C" void kernel_launch(void* const* d_in, const int* in_sizes, int n_in,
                              void* d_out, int out_size)
{
    const float* x  = (const float*)d_in[0];
    const float* Wr = (const float*)d_in[1];
    const float* Ww = (const float*)d_in[2];
    const float* Wk = (const float*)d_in[3];
    const float* Wv = (const float*)d_in[4];
    const float* Wo = (const float*)d_in[5];
    const float* td = (const float*)d_in[6];
    float* out = (float*)d_out;

    float *bk, *be, *br, *bv;
    cudaGetSymbolAddress((void**)&bk, g_k);
    cudaGetSymbolAddress((void**)&be, g_e);
    cudaGetSymbolAddress((void**)&br, g_r);
    cudaGetSymbolAddress((void**)&bv, g_v);

    dim3 grid(kD / 128, kM / 128);   // (16, 128)
    dim3 blk(256);

    // k = x @ Wk^T
    sgemm_nt<EPI_NONE><<<grid, blk>>>(x, Wk, bk, nullptr, kM, kD, kD);
    // ewk = exp(k - exp(x @ Ww^T))   (fused epilogue reads k buffer)
    sgemm_nt<EPI_EWK><<<grid, blk>>>(x, Ww, be, bk, kM, kD, kD);
    // r = sigmoid(x @ Wr^T)
    sgemm_nt<EPI_SIGMOID><<<grid, blk>>>(x, Wr, br, nullptr, kM, kD, kD);
    // v = x @ Wv^T
    sgemm_nt<EPI_NONE><<<grid, blk>>>(x, Wv, bv, nullptr, kM, kD, kD);

    // WKV scan; y overwrites g_k (k no longer needed). Also writes final_state
    // at the tail of d_out: [B*S*D .. B*S*D + 2*B*D)
    scan_kernel<<<(kB * kD) / 256, 256>>>(be, bv, br, td, bk,
                                          out + (size_t)kM * kD);

    // out = y @ Wo^T
    sgemm_nt<EPI_NONE><<<grid, blk>>>(bk, Wo, out, nullptr, kM, kD, kD);
}

// round 3
// speedup vs baseline: 3.2694x; 3.2694x over previous
#include <cuda_runtime.h>
#include <math.h>
#include <stdint.h>

// Problem dims
constexpr int kB = 4;
constexpr int kS = 4096;
constexpr int kD = 2048;
constexpr int kM = kB * kS;          // 16384 rows

// GEMM tiling: 128x128x32 CTA tile, 8 warps (2 M x 4 N), warp tile 64x32
constexpr int TM = 128;
constexpr int TN = 128;
constexpr int TK = 32;
constexpr int ROWSTRIDE = 36;                       // 32 + 4 pad floats
constexpr int STAGE_FLOATS = (TM + TN) * ROWSTRIDE; // 9216
constexpr int SMEM_BYTES = 2 * STAGE_FLOATS * 4;    // 73728

// Scan blocking
constexpr int NCH = 64;
constexpr int LCH = kS / NCH;        // 64

// Scratch (device globals: allocation-free rule)
__device__ float g_k[(size_t)kM * kD];        // k, later y
__device__ float g_e[(size_t)kM * kD];        // ewk
__device__ float g_r[(size_t)kM * kD];        // r
__device__ float g_v[(size_t)kM * kD];        // v
__device__ float g_xr[(size_t)kM * kD];       // x rounded to tf32
__device__ float g_w[5][(size_t)kD * kD];     // rounded weights
__device__ float g_carry[(size_t)kB * NCH * 2 * kD];

enum { EPI_NONE = 0, EPI_SIGMOID = 1, EPI_EWK = 2 };

// ---------------------------------------------------------------- helpers
__device__ __forceinline__ uint32_t smem_u32(const void* p) {
    return (uint32_t)__cvta_generic_to_shared(p);
}
__device__ __forceinline__ float tf32_rna(float x) {
    uint32_t u;
    asm("cvt.rna.tf32.f32 %0, %1;" : "=r"(u) : "f"(x));
    return __uint_as_float(u);
}

// ---------------------------------------------------------------- rounding
__global__ void round_tf32_kernel(const float* __restrict__ in,
                                  float* __restrict__ out, int n4) {
    int i = blockIdx.x * blockDim.x + threadIdx.x;
    if (i < n4) {
        float4 v = ((const float4*)in)[i];
        v.x = tf32_rna(v.x); v.y = tf32_rna(v.y);
        v.z = tf32_rna(v.z); v.w = tf32_rna(v.w);
        ((float4*)out)[i] = v;
    }
}

// ---------------------------------------------------------------- mma GEMM
// C[M,N] = A[M,K] @ W[N,K]^T  (fp32 data pre-rounded to tf32)
template <int EPI>
__global__ void __launch_bounds__(256)
mma_gemm(const float* __restrict__ A, const float* __restrict__ Wt,
         float* __restrict__ C, const float* __restrict__ aux, int Kk)
{
    extern __shared__ float smem[];

    const int tid = threadIdx.x;
    const int wid = tid >> 5;
    const int lane = tid & 31;
    const int g = lane >> 2;          // group 0..7
    const int tg = lane & 3;          // thread-in-group 0..3
    const int warpM = wid >> 2;       // 0..1
    const int warpN = wid & 3;        // 0..3
    const int bm = blockIdx.y * TM;
    const int bn = blockIdx.x * TN;

    float acc[4][4][4];
#pragma unroll
    for (int a = 0; a < 4; a++)
#pragma unroll
        for (int b = 0; b < 4; b++)
#pragma unroll
            for (int c = 0; c < 4; c++) acc[a][b][c] = 0.f;

    const int nchunk = Kk / TK;       // 64

    // Loader: 2048 x 16B per chunk (A:1024, B:1024), 8 per thread
    auto load_stage = [&](int s, int c) {
        float* Sa = smem + s * STAGE_FLOATS;
        float* Sb = Sa + TM * ROWSTRIDE;
        const int k0 = c * TK;
#pragma unroll
        for (int it = 0; it < 8; it++) {
            int i = tid + it * 256;
            int isB = i >> 10;                 // 0..3 -> A, 4..7 -> B
            int r = (i >> 3) & 127;
            int cc = i & 7;
            const float* gp = (isB ? Wt + (size_t)(bn + r) * Kk
                                   : A + (size_t)(bm + r) * Kk) + k0 + cc * 4;
            float* sp = (isB ? Sb : Sa) + r * ROWSTRIDE + cc * 4;
            asm volatile("cp.async.cg.shared.global [%0], [%1], 16;"
                         :: "r"(smem_u32(sp)), "l"(gp));
        }
    };

    load_stage(0, 0);
    asm volatile("cp.async.commit_group;" ::: "memory");
    load_stage(1, 1);
    asm volatile("cp.async.commit_group;" ::: "memory");

    for (int c = 0; c < nchunk; c++) {
        asm volatile("cp.async.wait_group 1;" ::: "memory");
        __syncthreads();

        const float* Sa = smem + (c & 1) * STAGE_FLOATS;
        const float* Sb = Sa + TM * ROWSTRIDE;

#pragma unroll
        for (int kk = 0; kk < TK; kk += 8) {
            uint32_t af[4][4];
            uint32_t bf[4][2];
#pragma unroll
            for (int mi = 0; mi < 4; mi++) {
                const int r0 = warpM * 64 + mi * 16 + g;
                af[mi][0] = __float_as_uint(Sa[r0 * ROWSTRIDE + kk + tg]);
                af[mi][1] = __float_as_uint(Sa[(r0 + 8) * ROWSTRIDE + kk + tg]);
                af[mi][2] = __float_as_uint(Sa[r0 * ROWSTRIDE + kk + tg + 4]);
                af[mi][3] = __float_as_uint(Sa[(r0 + 8) * ROWSTRIDE + kk + tg + 4]);
            }
#pragma unroll
            for (int ni = 0; ni < 4; ni++) {
                const int cn = warpN * 32 + ni * 8 + g;
                bf[ni][0] = __float_as_uint(Sb[cn * ROWSTRIDE + kk + tg]);
                bf[ni][1] = __float_as_uint(Sb[cn * ROWSTRIDE + kk + tg + 4]);
            }
#pragma unroll
            for (int mi = 0; mi < 4; mi++)
#pragma unroll
                for (int ni = 0; ni < 4; ni++) {
                    asm volatile(
                        "mma.sync.aligned.m16n8k8.row.col.f32.tf32.tf32.f32 "
                        "{%0,%1,%2,%3}, {%4,%5,%6,%7}, {%8,%9}, {%0,%1,%2,%3};"
                        : "+f"(acc[mi][ni][0]), "+f"(acc[mi][ni][1]),
                          "+f"(acc[mi][ni][2]), "+f"(acc[mi][ni][3])
                        : "r"(af[mi][0]), "r"(af[mi][1]),
                          "r"(af[mi][2]), "r"(af[mi][3]),
                          "r"(bf[ni][0]), "r"(bf[ni][1]));
                }
        }

        __syncthreads();                      // done reading stage (c&1)
        if (c + 2 < nchunk) load_stage(c & 1, c + 2);
        asm volatile("cp.async.commit_group;" ::: "memory");
    }
    asm volatile("cp.async.wait_group 0;" ::: "memory");

    // ---- epilogue: fragment layout c0,c1=(g, 2tg/2tg+1), c2,c3=(g+8, ...)
#pragma unroll
    for (int mi = 0; mi < 4; mi++) {
#pragma unroll
        for (int ni = 0; ni < 4; ni++) {
            const int n0 = bn + warpN * 32 + ni * 8 + 2 * tg;
#pragma unroll
            for (int h = 0; h < 2; h++) {
                const int m = bm + warpM * 64 + mi * 16 + g + h * 8;
                float t0 = acc[mi][ni][2 * h];
                float t1 = acc[mi][ni][2 * h + 1];
                const size_t idx = (size_t)m * kD + n0;
                if (EPI == EPI_SIGMOID) {
                    t0 = 1.f / (1.f + expf(-t0));
                    t1 = 1.f / (1.f + expf(-t1));
                } else if (EPI == EPI_EWK) {
                    float2 kk = *(const float2*)(aux + idx);
                    t0 = expf(kk.x - expf(t0));
                    t1 = expf(kk.y - expf(t1));
                }
                float2 o = {t0, t1};
                *(float2*)(C + idx) = o;
            }
        }
    }
}

// ---------------------------------------------------------------- blocked scan
__global__ void scan_phase1(const float* __restrict__ ewk,
                            const float* __restrict__ v,
                            const float* __restrict__ td,
                            float* __restrict__ carry)
{
    const int idx = blockIdx.x * blockDim.x + threadIdx.x;  // B*NCH*D
    const int d  = idx & (kD - 1);
    const int ch = (idx >> 11) & (NCH - 1);
    const int b  = idx >> 17;
    const float decay = expf(td[d]);

    float num = 0.f, den = 0.f;
    const size_t base = ((size_t)b * kS + (size_t)ch * LCH) * kD + d;
#pragma unroll 4
    for (int s = 0; s < LCH; s++) {
        const size_t i = base + (size_t)s * kD;
        const float e = ewk[i];
        const float vv = v[i];
        num = decay * num + e * vv;
        den = decay * den + e;
    }
    const size_t ci = (((size_t)b * NCH + ch) * 2) * kD + d;
    carry[ci] = num;
    carry[ci + kD] = den;
}

__global__ void scan_phase2(const float* __restrict__ td,
                            float* __restrict__ carry,
                            float* __restrict__ state_out)
{
    const int idx = blockIdx.x * blockDim.x + threadIdx.x;  // B*D
    const int d = idx & (kD - 1);
    const int b = idx >> 11;
    const float dl = expf(td[d] * (float)LCH);   // decay^LCH

    float num = 0.f, den = 0.f;
    for (int ch = 0; ch < NCH; ch++) {
        const size_t i0 = (((size_t)b * NCH + ch) * 2) * kD + d;
        const float cn = carry[i0];
        const float cd = carry[i0 + kD];
        carry[i0] = num;          // exclusive prefix (state before chunk)
        carry[i0 + kD] = den;
        num = dl * num + cn;
        den = dl * den + cd;
    }
    state_out[(size_t)b * 2 * kD + d] = num;
    state_out[(size_t)b * 2 * kD + kD + d] = den;
}

__global__ void scan_phase3(const float* __restrict__ ewk,
                            const float* __restrict__ v,
                            const float* __restrict__ r,
                            const float* __restrict__ td,
                            const float* __restrict__ carry,
                            float* __restrict__ y)
{
    const int idx = blockIdx.x * blockDim.x + threadIdx.x;  // B*NCH*D
    const int d  = idx & (kD - 1);
    const int ch = (idx >> 11) & (NCH - 1);
    const int b  = idx >> 17;
    const float decay = expf(td[d]);

    const size_t ci = (((size_t)b * NCH + ch) * 2) * kD + d;
    float num = carry[ci];
    float den = carry[ci + kD];

    const size_t base = ((size_t)b * kS + (size_t)ch * LCH) * kD + d;
#pragma unroll 4
    for (int s = 0; s < LCH; s++) {
        const size_t i = base + (size_t)s * kD;
        const float e = ewk[i];
        const float vv = v[i];
        const float rr = r[i];
        num = decay * num + e * vv;
        den = decay * den + e;
        y[i] = tf32_rna(rr * (num / (den + 1e-8f)));
    }
}

// ---------------------------------------------------------------- launch
extern "C" void kernel_launch(void* const* d_in, const int* in_sizes, int n_in,
                              void* d_out, int out_size)
{
    const float* x  = (const float*)d_in[0];
    const float* Wr = (const float*)d_in[1];
    const float* Ww = (const float*)d_in[2];
    const float* Wk = (const float*)d_in[3];
    const float* Wv = (const float*)d_in[4];
    const float* Wo = (const float*)d_in[5];
    const float* td = (const float*)d_in[6];
    float* out = (float*)d_out;

    float *bk, *be, *br, *bv, *bxr, *bw, *bcar;
    cudaGetSymbolAddress((void**)&bk,  g_k);
    cudaGetSymbolAddress((void**)&be,  g_e);
    cudaGetSymbolAddress((void**)&br,  g_r);
    cudaGetSymbolAddress((void**)&bv,  g_v);
    cudaGetSymbolAddress((void**)&bxr, g_xr);
    cudaGetSymbolAddress((void**)&bw,  g_w);
    cudaGetSymbolAddress((void**)&bcar, g_carry);

    float* wR = bw + 0 * (size_t)kD * kD;
    float* wW = bw + 1 * (size_t)kD * kD;
    float* wK = bw + 2 * (size_t)kD * kD;
    float* wV = bw + 3 * (size_t)kD * kD;
    float* wO = bw + 4 * (size_t)kD * kD;

    cudaFuncSetAttribute(mma_gemm<EPI_NONE>,
                         cudaFuncAttributeMaxDynamicSharedMemorySize, SMEM_BYTES);
    cudaFuncSetAttribute(mma_gemm<EPI_SIGMOID>,
                         cudaFuncAttributeMaxDynamicSharedMemorySize, SMEM_BYTES);
    cudaFuncSetAttribute(mma_gemm<EPI_EWK>,
                         cudaFuncAttributeMaxDynamicSharedMemorySize, SMEM_BYTES);

    // Round operands to tf32 (RNA) so the in-MMA truncation is unbiased
    const int nx4 = (kM / 4) * kD;
    const int nw4 = (kD / 4) * kD;
    round_tf32_kernel<<<nx4 / 256, 256>>>(x, bxr, nx4);
    round_tf32_kernel<<<nw4 / 256, 256>>>(Wr, wR, nw4);
    round_tf32_kernel<<<nw4 / 256, 256>>>(Ww, wW, nw4);
    round_tf32_kernel<<<nw4 / 256, 256>>>(Wk, wK, nw4);
    round_tf32_kernel<<<nw4 / 256, 256>>>(Wv, wV, nw4);
    round_tf32_kernel<<<nw4 / 256, 256>>>(Wo, wO, nw4);

    dim3 gg(kD / TN, kM / TM);    // (16, 128)

    // k = x @ Wk^T
    mma_gemm<EPI_NONE><<<gg, 256, SMEM_BYTES>>>(bxr, wK, bk, nullptr, kD);
    // ewk = exp(k - exp(x @ Ww^T))
    mma_gemm<EPI_EWK><<<gg, 256, SMEM_BYTES>>>(bxr, wW, be, bk, kD);
    // r = sigmoid(x @ Wr^T)
    mma_gemm<EPI_SIGMOID><<<gg, 256, SMEM_BYTES>>>(bxr, wR, br, nullptr, kD);
    // v = x @ Wv^T
    mma_gemm<EPI_NONE><<<gg, 256, SMEM_BYTES>>>(bxr, wV, bv, nullptr, kD);

    // Blocked WKV scan; y overwrites g_k. Final state at d_out tail.
    scan_phase1<<<(kB * NCH * kD) / 256, 256>>>(be, bv, td, bcar);
    scan_phase2<<<(kB * kD) / 256, 256>>>(td, bcar, out + (size_t)kM * kD);
    scan_phase3<<<(kB * NCH * kD) / 256, 256>>>(be, bv, br, td, bcar, bk);

    // out = y @ Wo^T
    mma_gemm<EPI_NONE><<<gg, 256, SMEM_BYTES>>>(bk, wO, out, nullptr, kD);
}

// round 4
// speedup vs baseline: 7.8175x; 2.3911x over previous
#include <cuda_runtime.h>
#include <cuda_fp16.h>
#include <math.h>
#include <stdint.h>

// Problem dims
constexpr int kB = 4;
constexpr int kS = 4096;
constexpr int kD = 2048;
constexpr int kM = kB * kS;          // 16384 rows

// GEMM tiling: 128x128x64 CTA tile (fp16), 8 warps (2 M x 4 N), warp 64x32
constexpr int TM = 128;
constexpr int TN = 128;
constexpr int TK = 64;                              // 64 halves = 128 B rows
constexpr int STAGE_BYTES = (TM + TN) * 128;        // 32 KB
constexpr int SMEM_BYTES = 2 * STAGE_BYTES;         // 64 KB

// Scan blocking
constexpr int NCH = 64;
constexpr int LCH = kS / NCH;        // 64

// Scratch (device globals: allocation-free rule)
__device__ float  g_k[(size_t)kM * kD];       // k (fp32, aux for ewk)
__device__ float  g_e[(size_t)kM * kD];       // ewk
__device__ float  g_r[(size_t)kM * kD];       // r
__device__ float  g_v[(size_t)kM * kD];       // v
__device__ __half g_xh[(size_t)kM * kD];      // x in fp16
__device__ __half g_wh[5][(size_t)kD * kD];   // weights in fp16
__device__ __half g_yh[(size_t)kM * kD];      // y in fp16
__device__ float  g_carry[(size_t)kB * NCH * 2 * kD];

enum { EPI_NONE = 0, EPI_SIGMOID = 1, EPI_EWK = 2 };

// ---------------------------------------------------------------- helpers
__device__ __forceinline__ uint32_t smem_u32(const void* p) {
    return (uint32_t)__cvta_generic_to_shared(p);
}

// ---------------------------------------------------------------- f32 -> f16
__global__ void f2h_kernel(const float* __restrict__ in,
                           __half* __restrict__ out, int n4) {
    int i = blockIdx.x * blockDim.x + threadIdx.x;
    if (i < n4) {
        float4 v = ((const float4*)in)[i];
        __half2 h0 = __floats2half2_rn(v.x, v.y);
        __half2 h1 = __floats2half2_rn(v.z, v.w);
        ((__half2*)out)[2 * i] = h0;
        ((__half2*)out)[2 * i + 1] = h1;
    }
}

// Convert all 5 weights in one launch (grid.y selects the weight)
__global__ void f2h_weights(const float* __restrict__ w0,
                            const float* __restrict__ w1,
                            const float* __restrict__ w2,
                            const float* __restrict__ w3,
                            const float* __restrict__ w4,
                            __half* __restrict__ out, int n4) {
    const float* in;
    switch (blockIdx.y) {
        case 0: in = w0; break;
        case 1: in = w1; break;
        case 2: in = w2; break;
        case 3: in = w3; break;
        default: in = w4; break;
    }
    __half* o = out + (size_t)blockIdx.y * kD * kD;
    int i = blockIdx.x * blockDim.x + threadIdx.x;
    if (i < n4) {
        float4 v = ((const float4*)in)[i];
        ((__half2*)o)[2 * i]     = __floats2half2_rn(v.x, v.y);
        ((__half2*)o)[2 * i + 1] = __floats2half2_rn(v.z, v.w);
    }
}

// ---------------------------------------------------------------- fp16 GEMM
// C[M,N] = A[M,K] @ W[N,K]^T, fp16 operands, fp32 accumulate.
// smem: 128-byte rows, SW128 XOR swizzle (16B chunk index ^= row&7).
template <int EPI>
__global__ void __launch_bounds__(256, 2)
mma_gemm(const __half* __restrict__ A, const __half* __restrict__ Wt,
         float* __restrict__ C, const float* __restrict__ aux, int Kk)
{
    extern __shared__ char smem[];

    const int tid = threadIdx.x;
    const int wid = tid >> 5;
    const int lane = tid & 31;
    const int g = lane >> 2;          // 0..7
    const int tg = lane & 3;          // 0..3
    const int warpM = wid >> 2;       // 0..1
    const int warpN = wid & 3;        // 0..3
    const int bm = blockIdx.y * TM;
    const int bn = blockIdx.x * TN;

    float acc[4][4][4];
#pragma unroll
    for (int a = 0; a < 4; a++)
#pragma unroll
        for (int b = 0; b < 4; b++)
#pragma unroll
            for (int c = 0; c < 4; c++) acc[a][b][c] = 0.f;

    const int nchunk = Kk / TK;       // 32

    // Loader: 2048 x 16B per chunk (A rows 0..127, B rows 0..127), 8/thread
    auto load_stage = [&](int s, int c) {
        char* base = smem + s * STAGE_BYTES;
        const int k0 = c * TK;
#pragma unroll
        for (int it = 0; it < 8; it++) {
            int i = tid + it * 256;
            int isB = i >> 10;
            int r = (i >> 3) & 127;
            int cc = i & 7;
            const __half* gp = (isB ? Wt + (size_t)(bn + r) * Kk
                                    : A + (size_t)(bm + r) * Kk) + k0 + cc * 8;
            char* sp = base + (isB ? TM * 128 : 0) + r * 128 +
                       ((cc ^ (r & 7)) << 4);
            asm volatile("cp.async.cg.shared.global [%0], [%1], 16;"
                         :: "r"(smem_u32(sp)), "l"(gp));
        }
    };

    load_stage(0, 0);
    asm volatile("cp.async.commit_group;" ::: "memory");
    load_stage(1, 1);
    asm volatile("cp.async.commit_group;" ::: "memory");

    const uint32_t xora = (uint32_t)g << 4;   // swizzle XOR for all frag reads

    for (int c = 0; c < nchunk; c++) {
        asm volatile("cp.async.wait_group 1;" ::: "memory");
        __syncthreads();

        const char* Sa = smem + (c & 1) * STAGE_BYTES;
        const char* Sb = Sa + TM * 128;

#pragma unroll
        for (int ks = 0; ks < 4; ks++) {              // 4 x k16 per chunk
            const uint32_t o0 = (uint32_t)(32 * ks + 4 * tg) ^ xora;
            const uint32_t o1 = (uint32_t)(32 * ks + 16 + 4 * tg) ^ xora;
            uint32_t af[4][4];
            uint32_t bf[4][2];
#pragma unroll
            for (int mi = 0; mi < 4; mi++) {
                const int r0 = warpM * 64 + mi * 16 + g;
                af[mi][0] = *(const uint32_t*)(Sa + r0 * 128 + o0);
                af[mi][1] = *(const uint32_t*)(Sa + (r0 + 8) * 128 + o0);
                af[mi][2] = *(const uint32_t*)(Sa + r0 * 128 + o1);
                af[mi][3] = *(const uint32_t*)(Sa + (r0 + 8) * 128 + o1);
            }
#pragma unroll
            for (int ni = 0; ni < 4; ni++) {
                const int cn = warpN * 32 + ni * 8 + g;
                bf[ni][0] = *(const uint32_t*)(Sb + cn * 128 + o0);
                bf[ni][1] = *(const uint32_t*)(Sb + cn * 128 + o1);
            }
#pragma unroll
            for (int mi = 0; mi < 4; mi++)
#pragma unroll
                for (int ni = 0; ni < 4; ni++) {
                    asm volatile(
                        "mma.sync.aligned.m16n8k16.row.col.f32.f16.f16.f32 "
                        "{%0,%1,%2,%3}, {%4,%5,%6,%7}, {%8,%9}, {%0,%1,%2,%3};"
                        : "+f"(acc[mi][ni][0]), "+f"(acc[mi][ni][1]),
                          "+f"(acc[mi][ni][2]), "+f"(acc[mi][ni][3])
                        : "r"(af[mi][0]), "r"(af[mi][1]),
                          "r"(af[mi][2]), "r"(af[mi][3]),
                          "r"(bf[ni][0]), "r"(bf[ni][1]));
                }
        }

        __syncthreads();
        if (c + 2 < nchunk) load_stage(c & 1, c + 2);
        asm volatile("cp.async.commit_group;" ::: "memory");
    }
    asm volatile("cp.async.wait_group 0;" ::: "memory");

    // ---- epilogue (fragment: c0,c1 = row g; c2,c3 = row g+8; cols 2tg,2tg+1)
#pragma unroll
    for (int mi = 0; mi < 4; mi++) {
#pragma unroll
        for (int ni = 0; ni < 4; ni++) {
            const int n0 = bn + warpN * 32 + ni * 8 + 2 * tg;
#pragma unroll
            for (int h = 0; h < 2; h++) {
                const int m = bm + warpM * 64 + mi * 16 + g + h * 8;
                float t0 = acc[mi][ni][2 * h];
                float t1 = acc[mi][ni][2 * h + 1];
                const size_t idx = (size_t)m * kD + n0;
                if (EPI == EPI_SIGMOID) {
                    t0 = 1.f / (1.f + expf(-t0));
                    t1 = 1.f / (1.f + expf(-t1));
                } else if (EPI == EPI_EWK) {
                    float2 kk = *(const float2*)(aux + idx);
                    t0 = expf(kk.x - expf(t0));
                    t1 = expf(kk.y - expf(t1));
                }
                float2 o = {t0, t1};
                *(float2*)(C + idx) = o;
            }
        }
    }
}

// ---------------------------------------------------------------- blocked scan
__global__ void scan_phase1(const float* __restrict__ ewk,
                            const float* __restrict__ v,
                            const float* __restrict__ td,
                            float* __restrict__ carry)
{
    const int idx = blockIdx.x * blockDim.x + threadIdx.x;  // B*NCH*D
    const int d  = idx & (kD - 1);
    const int ch = (idx >> 11) & (NCH - 1);
    const int b  = idx >> 17;
    const float decay = expf(td[d]);

    float num = 0.f, den = 0.f;
    const size_t base = ((size_t)b * kS + (size_t)ch * LCH) * kD + d;
#pragma unroll 4
    for (int s = 0; s < LCH; s++) {
        const size_t i = base + (size_t)s * kD;
        const float e = ewk[i];
        const float vv = v[i];
        num = decay * num + e * vv;
        den = decay * den + e;
    }
    const size_t ci = (((size_t)b * NCH + ch) * 2) * kD + d;
    carry[ci] = num;
    carry[ci + kD] = den;
}

__global__ void scan_phase2(const float* __restrict__ td,
                            float* __restrict__ carry,
                            float* __restrict__ state_out)
{
    const int idx = blockIdx.x * blockDim.x + threadIdx.x;  // B*D
    const int d = idx & (kD - 1);
    const int b = idx >> 11;
    const float dl = expf(td[d] * (float)LCH);   // decay^LCH

    float num = 0.f, den = 0.f;
    for (int ch = 0; ch < NCH; ch++) {
        const size_t i0 = (((size_t)b * NCH + ch) * 2) * kD + d;
        const float cn = carry[i0];
        const float cd = carry[i0 + kD];
        carry[i0] = num;          // exclusive prefix (state before chunk)
        carry[i0 + kD] = den;
        num = dl * num + cn;
        den = dl * den + cd;
    }
    state_out[(size_t)b * 2 * kD + d] = num;
    state_out[(size_t)b * 2 * kD + kD + d] = den;
}

__global__ void scan_phase3(const float* __restrict__ ewk,
                            const float* __restrict__ v,
                            const float* __restrict__ r,
                            const float* __restrict__ td,
                            const float* __restrict__ carry,
                            __half* __restrict__ y)
{
    const int idx = blockIdx.x * blockDim.x + threadIdx.x;  // B*NCH*D
    const int d  = idx & (kD - 1);
    const int ch = (idx >> 11) & (NCH - 1);
    const int b  = idx >> 17;
    const float decay = expf(td[d]);

    const size_t ci = (((size_t)b * NCH + ch) * 2) * kD + d;
    float num = carry[ci];
    float den = carry[ci + kD];

    const size_t base = ((size_t)b * kS + (size_t)ch * LCH) * kD + d;
#pragma unroll 4
    for (int s = 0; s < LCH; s++) {
        const size_t i = base + (size_t)s * kD;
        const float e = ewk[i];
        const float vv = v[i];
        const float rr = r[i];
        num = decay * num + e * vv;
        den = decay * den + e;
        y[i] = __float2half_rn(rr * (num / (den + 1e-8f)));
    }
}

// ---------------------------------------------------------------- launch
extern "C" void kernel_launch(void* const* d_in, const int* in_sizes, int n_in,
                              void* d_out, int out_size)
{
    const float* x  = (const float*)d_in[0];
    const float* Wr = (const float*)d_in[1];
    const float* Ww = (const float*)d_in[2];
    const float* Wk = (const float*)d_in[3];
    const float* Wv = (const float*)d_in[4];
    const float* Wo = (const float*)d_in[5];
    const float* td = (const float*)d_in[6];
    float* out = (float*)d_out;

    float *bk, *be, *br, *bv, *bcar;
    __half *bxh, *bwh, *byh;
    cudaGetSymbolAddress((void**)&bk,  g_k);
    cudaGetSymbolAddress((void**)&be,  g_e);
    cudaGetSymbolAddress((void**)&br,  g_r);
    cudaGetSymbolAddress((void**)&bv,  g_v);
    cudaGetSymbolAddress((void**)&bxh, g_xh);
    cudaGetSymbolAddress((void**)&bwh, g_wh);
    cudaGetSymbolAddress((void**)&byh, g_yh);
    cudaGetSymbolAddress((void**)&bcar, g_carry);

    __half* wR = bwh + 0 * (size_t)kD * kD;
    __half* wW = bwh + 1 * (size_t)kD * kD;
    __half* wK = bwh + 2 * (size_t)kD * kD;
    __half* wV = bwh + 3 * (size_t)kD * kD;
    __half* wO = bwh + 4 * (size_t)kD * kD;

    cudaFuncSetAttribute(mma_gemm<EPI_NONE>,
                         cudaFuncAttributeMaxDynamicSharedMemorySize, SMEM_BYTES);
    cudaFuncSetAttribute(mma_gemm<EPI_SIGMOID>,
                         cudaFuncAttributeMaxDynamicSharedMemorySize, SMEM_BYTES);
    cudaFuncSetAttribute(mma_gemm<EPI_EWK>,
                         cudaFuncAttributeMaxDynamicSharedMemorySize, SMEM_BYTES);

    // launch 0: x -> fp16 ; launch 1: all 5 weights -> fp16
    const int nx4 = (kM / 4) * kD;
    const int nw4 = (kD / 4) * kD;
    f2h_kernel<<<nx4 / 256, 256>>>(x, bxh, nx4);
    dim3 wg(nw4 / 256, 5);
    f2h_weights<<<wg, 256>>>(Wr, Ww, Wk, Wv, Wo, bwh, nw4);

    dim3 gg(kD / TN, kM / TM);    // (16, 128)

    // launches 2..5 (5 = v GEMM -> lands in ncu window)
    mma_gemm<EPI_NONE><<<gg, 256, SMEM_BYTES>>>(bxh, wK, bk, nullptr, kD);
    mma_gemm<EPI_EWK><<<gg, 256, SMEM_BYTES>>>(bxh, wW, be, bk, kD);
    mma_gemm<EPI_SIGMOID><<<gg, 256, SMEM_BYTES>>>(bxh, wR, br, nullptr, kD);
    mma_gemm<EPI_NONE><<<gg, 256, SMEM_BYTES>>>(bxh, wV, bv, nullptr, kD);

    // Blocked WKV scan; final state at d_out tail, y in fp16.
    scan_phase1<<<(kB * NCH * kD) / 256, 256>>>(be, bv, td, bcar);
    scan_phase2<<<(kB * kD) / 256, 256>>>(td, bcar, out + (size_t)kM * kD);
    scan_phase3<<<(kB * NCH * kD) / 256, 256>>>(be, bv, br, td, bcar, byh);

    // out = y @ Wo^T
    mma_gemm<EPI_NONE><<<gg, 256, SMEM_BYTES>>>(byh, wO, out, nullptr, kD);
}

// round 9
// speedup vs baseline: 8.2863x; 1.0600x over previous
#include <cuda_runtime.h>
#include <cuda_fp16.h>
#include <math.h>
#include <stdint.h>

// Problem dims
constexpr int kB = 4;
constexpr int kS = 4096;
constexpr int kD = 2048;
constexpr int kM = kB * kS;          // 16384 rows

// GEMM tiling: 128x128x64 CTA tile (fp16), 8 warps (2 M x 4 N), warp 64x32
constexpr int TM = 128;
constexpr int TN = 128;
constexpr int TK = 64;                              // 64 halves = 128 B rows
constexpr int STAGE_BYTES = (TM + TN) * 128;        // 32 KB
constexpr int STAGES = 3;
constexpr int SMEM_BYTES = STAGES * STAGE_BYTES;    // 96 KB

// Scan blocking
constexpr int NCH = 64;
constexpr int LCH = kS / NCH;        // 64

// Scratch (device globals: allocation-free rule)
__device__ float  g_k[(size_t)kM * kD];       // k (fp32, aux for ewk)
__device__ float  g_e[(size_t)kM * kD];       // ewk
__device__ float  g_r[(size_t)kM * kD];       // r
__device__ float  g_v[(size_t)kM * kD];       // v
__device__ __half g_xh[(size_t)kM * kD];      // x in fp16
__device__ __half g_wh[5][(size_t)kD * kD];   // weights in fp16
__device__ __half g_yh[(size_t)kM * kD];      // y in fp16
__device__ float  g_carry[(size_t)kB * NCH * 2 * kD];

enum { EPI_NONE = 0, EPI_SIGMOID = 1, EPI_EWK = 2 };

// ---------------------------------------------------------------- helpers
__device__ __forceinline__ uint32_t smem_u32(const void* p) {
    return (uint32_t)__cvta_generic_to_shared(p);
}

// ---------------------------------------------------------------- f32 -> f16
__global__ void f2h_kernel(const float* __restrict__ in,
                           __half* __restrict__ out, int n4) {
    int i = blockIdx.x * blockDim.x + threadIdx.x;
    if (i < n4) {
        float4 v = ((const float4*)in)[i];
        ((__half2*)out)[2 * i]     = __floats2half2_rn(v.x, v.y);
        ((__half2*)out)[2 * i + 1] = __floats2half2_rn(v.z, v.w);
    }
}

__global__ void f2h_weights(const float* __restrict__ w0,
                            const float* __restrict__ w1,
                            const float* __restrict__ w2,
                            const float* __restrict__ w3,
                            const float* __restrict__ w4,
                            __half* __restrict__ out, int n4) {
    const float* in;
    switch (blockIdx.y) {
        case 0: in = w0; break;
        case 1: in = w1; break;
        case 2: in = w2; break;
        case 3: in = w3; break;
        default: in = w4; break;
    }
    __half* o = out + (size_t)blockIdx.y * kD * kD;
    int i = blockIdx.x * blockDim.x + threadIdx.x;
    if (i < n4) {
        float4 v = ((const float4*)in)[i];
        ((__half2*)o)[2 * i]     = __floats2half2_rn(v.x, v.y);
        ((__half2*)o)[2 * i + 1] = __floats2half2_rn(v.z, v.w);
    }
}

// ---------------------------------------------------------------- fp16 GEMM
// C[M,N] = A[M,K] @ W[N,K]^T, fp16 operands, fp32 accumulate.
// smem: 128-byte rows, SW128 XOR swizzle. 3-stage cp.async pipeline,
// one __syncthreads per chunk, ldmatrix.x4 fragment loads.
template <int EPI>
__global__ void __launch_bounds__(256, 2)
mma_gemm(const __half* __restrict__ A, const __half* __restrict__ Wt,
         float* __restrict__ C, const float* __restrict__ aux, int Kk)
{
    extern __shared__ char smem[];
    const uint32_t smem0 = smem_u32(smem);

    const int tid = threadIdx.x;
    const int wid = tid >> 5;
    const int lane = tid & 31;
    const int g = lane >> 2;          // 0..7
    const int tg = lane & 3;          // 0..3
    const int warpM = wid >> 2;       // 0..1
    const int warpN = wid & 3;        // 0..3
    const int bm = blockIdx.y * TM;
    const int bn = blockIdx.x * TN;

    float acc[4][4][4];
#pragma unroll
    for (int a = 0; a < 4; a++)
#pragma unroll
        for (int b = 0; b < 4; b++)
#pragma unroll
            for (int c = 0; c < 4; c++) acc[a][b][c] = 0.f;

    const int nchunk = Kk / TK;       // 32

    // ldmatrix per-lane address precompute.
    // A (x4): matrices m0..m3 = (rows0-7,k0-7),(rows8-15,k0-7),
    //         (rows0-7,k8-15),(rows8-15,k8-15)
    //   lane l -> row bit = (l>>3)&1, k-half = (l>>4)&1
    // B (x4 over an n16 pair): m0..m3 = (n0-7,k0-7),(n0-7,k8-15),
    //         (n8-15,k0-7),(n8-15,k8-15)
    //   lane l -> k-half = (l>>3)&1, row bit = (l>>4)&1
    const int arow_l = ((lane >> 3) & 1) * 8 + (lane & 7);
    const int akh    = (lane >> 4) & 1;
    const int brow_l = ((lane >> 4) & 1) * 8 + (lane & 7);
    const int bkh    = (lane >> 3) & 1;

    uint32_t aBase[4], aSw[4];
#pragma unroll
    for (int mi = 0; mi < 4; mi++) {
        const int r = warpM * 64 + mi * 16 + arow_l;
        aBase[mi] = (uint32_t)r * 128;
        aSw[mi] = (uint32_t)(r & 7);
    }
    uint32_t bBase[2], bSw[2];
#pragma unroll
    for (int p = 0; p < 2; p++) {
        const int r = warpN * 32 + p * 16 + brow_l;
        bBase[p] = (uint32_t)(TM * 128) + (uint32_t)r * 128;
        bSw[p] = (uint32_t)(r & 7);
    }

    // Loader: 2048 x 16B per chunk (A rows 0..127, B rows 0..127), 8/thread
    auto load_stage = [&](int s, int c) {
        char* base = smem + s * STAGE_BYTES;
        const int k0 = c * TK;
#pragma unroll
        for (int it = 0; it < 8; it++) {
            int i = tid + it * 256;
            int isB = i >> 10;
            int r = (i >> 3) & 127;
            int cc = i & 7;
            const __half* gp = (isB ? Wt + (size_t)(bn + r) * Kk
                                    : A + (size_t)(bm + r) * Kk) + k0 + cc * 8;
            char* sp = base + (isB ? TM * 128 : 0) + r * 128 +
                       ((cc ^ (r & 7)) << 4);
            asm volatile("cp.async.cg.shared.global [%0], [%1], 16;"
                         :: "r"(smem_u32(sp)), "l"(gp));
        }
    };

    load_stage(0, 0);
    asm volatile("cp.async.commit_group;" ::: "memory");
    load_stage(1, 1);
    asm volatile("cp.async.commit_group;" ::: "memory");

    int sc = 0;                       // compute stage (c % 3)
    int sl = 2;                       // load slot ((c+2) % 3)

    for (int c = 0; c < nchunk; c++) {
        asm volatile("cp.async.wait_group 1;" ::: "memory");
        __syncthreads();

        // Refill slot sl (holds tile c-1, consumed; proven by the barrier)
        if (c + 2 < nchunk) load_stage(sl, c + 2);
        asm volatile("cp.async.commit_group;" ::: "memory");

        const uint32_t st = smem0 + (uint32_t)sc * STAGE_BYTES;

#pragma unroll
        for (int ks = 0; ks < 4; ks++) {              // 4 x k16 per chunk
            uint32_t af[4][4];
            uint32_t bf[4][2];
#pragma unroll
            for (int mi = 0; mi < 4; mi++) {
                const uint32_t addr =
                    st + aBase[mi] + ((((uint32_t)(2 * ks + akh)) ^ aSw[mi]) << 4);
                asm volatile(
                    "ldmatrix.sync.aligned.m8n8.x4.shared.b16 "
                    "{%0,%1,%2,%3}, [%4];"
                    : "=r"(af[mi][0]), "=r"(af[mi][1]),
                      "=r"(af[mi][2]), "=r"(af[mi][3])
                    : "r"(addr));
            }
#pragma unroll
            for (int p = 0; p < 2; p++) {
                const uint32_t addr =
                    st + bBase[p] + ((((uint32_t)(2 * ks + bkh)) ^ bSw[p]) << 4);
                asm volatile(
                    "ldmatrix.sync.aligned.m8n8.x4.shared.b16 "
                    "{%0,%1,%2,%3}, [%4];"
                    : "=r"(bf[2 * p][0]), "=r"(bf[2 * p][1]),
                      "=r"(bf[2 * p + 1][0]), "=r"(bf[2 * p + 1][1])
                    : "r"(addr));
            }
#pragma unroll
            for (int mi = 0; mi < 4; mi++)
#pragma unroll
                for (int ni = 0; ni < 4; ni++) {
                    asm volatile(
                        "mma.sync.aligned.m16n8k16.row.col.f32.f16.f16.f32 "
                        "{%0,%1,%2,%3}, {%4,%5,%6,%7}, {%8,%9}, {%0,%1,%2,%3};"
                        : "+f"(acc[mi][ni][0]), "+f"(acc[mi][ni][1]),
                          "+f"(acc[mi][ni][2]), "+f"(acc[mi][ni][3])
                        : "r"(af[mi][0]), "r"(af[mi][1]),
                          "r"(af[mi][2]), "r"(af[mi][3]),
                          "r"(bf[ni][0]), "r"(bf[ni][1]));
                }
        }

        sc = (sc == 2) ? 0 : sc + 1;
        sl = (sl == 2) ? 0 : sl + 1;
    }
    asm volatile("cp.async.wait_group 0;" ::: "memory");

    // ---- epilogue (fragment: c0,c1 = row g; c2,c3 = row g+8; cols 2tg,2tg+1)
#pragma unroll
    for (int mi = 0; mi < 4; mi++) {
#pragma unroll
        for (int ni = 0; ni < 4; ni++) {
            const int n0 = bn + warpN * 32 + ni * 8 + 2 * tg;
#pragma unroll
            for (int h = 0; h < 2; h++) {
                const int m = bm + warpM * 64 + mi * 16 + g + h * 8;
                float t0 = acc[mi][ni][2 * h];
                float t1 = acc[mi][ni][2 * h + 1];
                const size_t idx = (size_t)m * kD + n0;
                if (EPI == EPI_SIGMOID) {
                    t0 = 1.f / (1.f + expf(-t0));
                    t1 = 1.f / (1.f + expf(-t1));
                } else if (EPI == EPI_EWK) {
                    float2 kk = *(const float2*)(aux + idx);
                    t0 = expf(kk.x - expf(t0));
                    t1 = expf(kk.y - expf(t1));
                }
                float2 o = {t0, t1};
                *(float2*)(C + idx) = o;
            }
        }
    }
}

// ---------------------------------------------------------------- blocked scan
__global__ void scan_phase1(const float* __restrict__ ewk,
                            const float* __restrict__ v,
                            const float* __restrict__ td,
                            float* __restrict__ carry)
{
    const int idx = blockIdx.x * blockDim.x + threadIdx.x;  // B*NCH*D
    const int d  = idx & (kD - 1);
    const int ch = (idx >> 11) & (NCH - 1);
    const int b  = idx >> 17;
    const float decay = expf(td[d]);

    float num = 0.f, den = 0.f;
    const size_t base = ((size_t)b * kS + (size_t)ch * LCH) * kD + d;
#pragma unroll 4
    for (int s = 0; s < LCH; s++) {
        const size_t i = base + (size_t)s * kD;
        const float e = ewk[i];
        const float vv = v[i];
        num = decay * num + e * vv;
        den = decay * den + e;
    }
    const size_t ci = (((size_t)b * NCH + ch) * 2) * kD + d;
    carry[ci] = num;
    carry[ci + kD] = den;
}

__global__ void scan_phase2(const float* __restrict__ td,
                            float* __restrict__ carry,
                            float* __restrict__ state_out)
{
    const int idx = blockIdx.x * blockDim.x + threadIdx.x;  // B*D
    const int d = idx & (kD - 1);
    const int b = idx >> 11;
    const float dl = expf(td[d] * (float)LCH);   // decay^LCH

    float num = 0.f, den = 0.f;
    for (int ch = 0; ch < NCH; ch++) {
        const size_t i0 = (((size_t)b * NCH + ch) * 2) * kD + d;
        const float cn = carry[i0];
        const float cd = carry[i0 + kD];
        carry[i0] = num;          // exclusive prefix (state before chunk)
        carry[i0 + kD] = den;
        num = dl * num + cn;
        den = dl * den + cd;
    }
    state_out[(size_t)b * 2 * kD + d] = num;
    state_out[(size_t)b * 2 * kD + kD + d] = den;
}

__global__ void scan_phase3(const float* __restrict__ ewk,
                            const float* __restrict__ v,
                            const float* __restrict__ r,
                            const float* __restrict__ td,
                            const float* __restrict__ carry,
                            __half* __restrict__ y)
{
    const int idx = blockIdx.x * blockDim.x + threadIdx.x;  // B*NCH*D
    const int d  = idx & (kD - 1);
    const int ch = (idx >> 11) & (NCH - 1);
    const int b  = idx >> 17;
    const float decay = expf(td[d]);

    const size_t ci = (((size_t)b * NCH + ch) * 2) * kD + d;
    float num = carry[ci];
    float den = carry[ci + kD];

    const size_t base = ((size_t)b * kS + (size_t)ch * LCH) * kD + d;
#pragma unroll 4
    for (int s = 0; s < LCH; s++) {
        const size_t i = base + (size_t)s * kD;
        const float e = ewk[i];
        const float vv = v[i];
        const float rr = r[i];
        num = decay * num + e * vv;
        den = decay * den + e;
        y[i] = __float2half_rn(rr * (num / (den + 1e-8f)));
    }
}

// ---------------------------------------------------------------- launch
extern "C" void kernel_launch(void* const* d_in, const int* in_sizes, int n_in,
                              void* d_out, int out_size)
{
    const float* x  = (const float*)d_in[0];
    const float* Wr = (const float*)d_in[1];
    const float* Ww = (const float*)d_in[2];
    const float* Wk = (const float*)d_in[3];
    const float* Wv = (const float*)d_in[4];
    const float* Wo = (const float*)d_in[5];
    const float* td = (const float*)d_in[6];
    float* out = (float*)d_out;

    float *bk, *be, *br, *bv, *bcar;
    __half *bxh, *bwh, *byh;
    cudaGetSymbolAddress((void**)&bk,  g_k);
    cudaGetSymbolAddress((void**)&be,  g_e);
    cudaGetSymbolAddress((void**)&br,  g_r);
    cudaGetSymbolAddress((void**)&bv,  g_v);
    cudaGetSymbolAddress((void**)&bxh, g_xh);
    cudaGetSymbolAddress((void**)&bwh, g_wh);
    cudaGetSymbolAddress((void**)&byh, g_yh);
    cudaGetSymbolAddress((void**)&bcar, g_carry);

    __half* wR = bwh + 0 * (size_t)kD * kD;
    __half* wW = bwh + 1 * (size_t)kD * kD;
    __half* wK = bwh + 2 * (size_t)kD * kD;
    __half* wV = bwh + 3 * (size_t)kD * kD;
    __half* wO = bwh + 4 * (size_t)kD * kD;

    cudaFuncSetAttribute(mma_gemm<EPI_NONE>,
                         cudaFuncAttributeMaxDynamicSharedMemorySize, SMEM_BYTES);
    cudaFuncSetAttribute(mma_gemm<EPI_SIGMOID>,
                         cudaFuncAttributeMaxDynamicSharedMemorySize, SMEM_BYTES);
    cudaFuncSetAttribute(mma_gemm<EPI_EWK>,
                         cudaFuncAttributeMaxDynamicSharedMemorySize, SMEM_BYTES);

    const int nx4 = (kM / 4) * kD;
    const int nw4 = (kD / 4) * kD;
    f2h_kernel<<<nx4 / 256, 256>>>(x, bxh, nx4);
    dim3 wg(nw4 / 256, 5);
    f2h_weights<<<wg, 256>>>(Wr, Ww, Wk, Wv, Wo, bwh, nw4);

    dim3 gg(kD / TN, kM / TM);    // (16, 128)

    // launches 2..5 (index 5 = v GEMM -> ncu window)
    mma_gemm<EPI_NONE><<<gg, 256, SMEM_BYTES>>>(bxh, wK, bk, nullptr, kD);
    mma_gemm<EPI_EWK><<<gg, 256, SMEM_BYTES>>>(bxh, wW, be, bk, kD);
    mma_gemm<EPI_SIGMOID><<<gg, 256, SMEM_BYTES>>>(bxh, wR, br, nullptr, kD);
    mma_gemm<EPI_NONE><<<gg, 256, SMEM_BYTES>>>(bxh, wV, bv, nullptr, kD);

    // Blocked WKV scan; final state at d_out tail, y in fp16.
    scan_phase1<<<(kB * NCH * kD) / 256, 256>>>(be, bv, td, bcar);
    scan_phase2<<<(kB * kD) / 256, 256>>>(td, bcar, out + (size_t)kM * kD);
    scan_phase3<<<(kB * NCH * kD) / 256, 256>>>(be, bv, br, td, bcar, byh);

    // out = y @ Wo^T
    mma_gemm<EPI_NONE><<<gg, 256, SMEM_BYTES>>>(byh, wO, out, nullptr, kD);
}

// round 10
// speedup vs baseline: 8.3590x; 1.0088x over previous
#include <cuda_runtime.h>
#include <cuda_fp16.h>
#include <math.h>
#include <stdint.h>

// Problem dims
constexpr int kB = 4;
constexpr int kS = 4096;
constexpr int kD = 2048;
constexpr int kM = kB * kS;          // 16384 rows

// GEMM tiling: 128x128x64 CTA tile (fp16), 8 warps (2 M x 4 N), warp 64x32
constexpr int TM = 128;
constexpr int TN = 128;
constexpr int TK = 64;                              // 64 halves = 128 B rows
constexpr int STAGE_BYTES = (TM + TN) * 128;        // 32 KB
constexpr int STAGES = 3;
constexpr int SMEM_BYTES = STAGES * STAGE_BYTES;    // 96 KB

// Scan blocking
constexpr int NCH = 64;
constexpr int LCH = kS / NCH;        // 64

// Scratch (device globals: allocation-free rule)
__device__ float  g_k[(size_t)kM * kD];       // k (fp32, aux for ewk)
__device__ float  g_e[(size_t)kM * kD];       // ewk
__device__ float  g_r[(size_t)kM * kD];       // r
__device__ float  g_v[(size_t)kM * kD];       // v
__device__ __half g_xh[(size_t)kM * kD];      // x in fp16
__device__ __half g_wh[5][(size_t)kD * kD];   // weights in fp16
__device__ __half g_yh[(size_t)kM * kD];      // y in fp16
__device__ float  g_carry[(size_t)kB * NCH * 2 * kD];

enum { EPI_NONE = 0, EPI_SIGMOID = 1, EPI_EWK = 2 };

// ---------------------------------------------------------------- helpers
__device__ __forceinline__ uint32_t smem_u32(const void* p) {
    return (uint32_t)__cvta_generic_to_shared(p);
}

// ---------------------------------------------------------------- f32 -> f16
__global__ void f2h_kernel(const float* __restrict__ in,
                           __half* __restrict__ out, int n4) {
    int i = blockIdx.x * blockDim.x + threadIdx.x;
    if (i < n4) {
        float4 v = ((const float4*)in)[i];
        ((__half2*)out)[2 * i]     = __floats2half2_rn(v.x, v.y);
        ((__half2*)out)[2 * i + 1] = __floats2half2_rn(v.z, v.w);
    }
}

__global__ void f2h_weights(const float* __restrict__ w0,
                            const float* __restrict__ w1,
                            const float* __restrict__ w2,
                            const float* __restrict__ w3,
                            const float* __restrict__ w4,
                            __half* __restrict__ out, int n4) {
    const float* in;
    switch (blockIdx.y) {
        case 0: in = w0; break;
        case 1: in = w1; break;
        case 2: in = w2; break;
        case 3: in = w3; break;
        default: in = w4; break;
    }
    __half* o = out + (size_t)blockIdx.y * kD * kD;
    int i = blockIdx.x * blockDim.x + threadIdx.x;
    if (i < n4) {
        float4 v = ((const float4*)in)[i];
        ((__half2*)o)[2 * i]     = __floats2half2_rn(v.x, v.y);
        ((__half2*)o)[2 * i + 1] = __floats2half2_rn(v.z, v.w);
    }
}

// ---------------------------------------------------------------- fp16 GEMM
// C[M,N] = A[M,K] @ W[N,K]^T, fp16 operands, fp32 accumulate.
// smem: 128-byte rows, SW128 XOR swizzle. 3-stage cp.async pipeline,
// one __syncthreads per chunk, ldmatrix.x4 with fully precomputed
// per-lane address constants (swizzle XOR = lane&7 for every fragment).
template <int EPI>
__global__ void __launch_bounds__(256, 2)
mma_gemm(const __half* __restrict__ A, const __half* __restrict__ Wt,
         float* __restrict__ C, const float* __restrict__ aux, int Kk)
{
    extern __shared__ char smem[];
    const uint32_t smem0 = smem_u32(smem);

    const int tid = threadIdx.x;
    const int wid = tid >> 5;
    const int lane = tid & 31;
    const int g = lane >> 2;          // 0..7
    const int tg = lane & 3;          // 0..3
    const int warpM = wid >> 2;       // 0..1
    const int warpN = wid & 3;        // 0..3
    const int bm = blockIdx.y * TM;
    const int bn = blockIdx.x * TN;

    float acc[4][4][4];
#pragma unroll
    for (int a = 0; a < 4; a++)
#pragma unroll
        for (int b = 0; b < 4; b++)
#pragma unroll
            for (int c = 0; c < 4; c++) acc[a][b][c] = 0.f;

    const int nchunk = Kk / TK;       // 32

    // ---- ldmatrix address constants.
    // A (x4): lane -> row-bit=(l>>3)&1, k-half=(l>>4)&1
    // B (x4): lane -> k-half=(l>>3)&1, row-bit=(l>>4)&1
    // Fragment row r always satisfies r&7 == lane&7 -> one swizzle XOR/lane.
    const int arow_l = ((lane >> 3) & 1) * 8 + (lane & 7);
    const int akh    = (lane >> 4) & 1;
    const int brow_l = ((lane >> 4) & 1) * 8 + (lane & 7);
    const int bkh    = (lane >> 3) & 1;
    const uint32_t sw = (uint32_t)(lane & 7);

    uint32_t aBase[4];                 // stage-relative row bases
#pragma unroll
    for (int mi = 0; mi < 4; mi++)
        aBase[mi] = (uint32_t)(warpM * 64 + mi * 16 + arow_l) * 128;
    uint32_t bBase[2];
#pragma unroll
    for (int p = 0; p < 2; p++)
        bBase[p] = (uint32_t)(TM * 128) +
                   (uint32_t)(warpN * 32 + p * 16 + brow_l) * 128;

    uint32_t aOffK[4], bOffK[4];       // per-ks 16B-chunk offsets (swizzled)
#pragma unroll
    for (int ks = 0; ks < 4; ks++) {
        aOffK[ks] = (((uint32_t)(2 * ks + akh)) ^ sw) << 4;
        bOffK[ks] = (((uint32_t)(2 * ks + bkh)) ^ sw) << 4;
    }

    // ---- loader constants: i = tid + 256*it -> row = r0 + 32*(it&3),
    // B-half at it>=4; cc and swizzle XOR fixed per thread.
    const int r0 = tid >> 3;
    const int cc = tid & 7;
    const uint32_t lsw = ((uint32_t)(cc ^ (r0 & 7))) << 4;
    const __half* gA0 = A + (size_t)(bm + r0) * Kk + cc * 8;
    const __half* gB0 = Wt + (size_t)(bn + r0) * Kk + cc * 8;
    const uint32_t spA0 = smem0 + (uint32_t)r0 * 128 + lsw;
    const uint32_t spB0 = spA0 + (uint32_t)(TM * 128);
    const size_t rowStride32 = (size_t)32 * Kk;

    auto load_stage = [&](int s, int c) {
        const uint32_t so = (uint32_t)s * STAGE_BYTES;
        const __half* gA = gA0 + (size_t)c * TK;
        const __half* gB = gB0 + (size_t)c * TK;
#pragma unroll
        for (int it = 0; it < 4; it++) {
            asm volatile("cp.async.cg.shared.global [%0], [%1], 16;"
                         :: "r"(spA0 + so + it * 32 * 128),
                            "l"(gA + it * rowStride32));
        }
#pragma unroll
        for (int it = 0; it < 4; it++) {
            asm volatile("cp.async.cg.shared.global [%0], [%1], 16;"
                         :: "r"(spB0 + so + it * 32 * 128),
                            "l"(gB + it * rowStride32));
        }
    };

    load_stage(0, 0);
    asm volatile("cp.async.commit_group;" ::: "memory");
    load_stage(1, 1);
    asm volatile("cp.async.commit_group;" ::: "memory");

    int sc = 0;                       // compute stage
    int sl = 2;                       // load slot

    for (int c = 0; c < nchunk; c++) {
        asm volatile("cp.async.wait_group 1;" ::: "memory");
        __syncthreads();

        // Refill slot sl (its old tile was consumed; barrier proves it)
        if (c + 2 < nchunk) load_stage(sl, c + 2);
        asm volatile("cp.async.commit_group;" ::: "memory");

        const uint32_t st = smem0 + (uint32_t)sc * STAGE_BYTES;
        uint32_t aSt[4], bSt[2];
#pragma unroll
        for (int mi = 0; mi < 4; mi++) aSt[mi] = st - smem0 + smem0 + aBase[mi];
#pragma unroll
        for (int p = 0; p < 2; p++) bSt[p] = st + bBase[p];
#pragma unroll
        for (int mi = 0; mi < 4; mi++) aSt[mi] = st + aBase[mi];

#pragma unroll
        for (int ks = 0; ks < 4; ks++) {              // 4 x k16 per chunk
            uint32_t af[4][4];
            uint32_t bf[4][2];
#pragma unroll
            for (int p = 0; p < 2; p++) {
                asm volatile(
                    "ldmatrix.sync.aligned.m8n8.x4.shared.b16 "
                    "{%0,%1,%2,%3}, [%4];"
                    : "=r"(bf[2 * p][0]), "=r"(bf[2 * p][1]),
                      "=r"(bf[2 * p + 1][0]), "=r"(bf[2 * p + 1][1])
                    : "r"(bSt[p] + bOffK[ks]));
            }
#pragma unroll
            for (int mi = 0; mi < 4; mi++) {
                asm volatile(
                    "ldmatrix.sync.aligned.m8n8.x4.shared.b16 "
                    "{%0,%1,%2,%3}, [%4];"
                    : "=r"(af[mi][0]), "=r"(af[mi][1]),
                      "=r"(af[mi][2]), "=r"(af[mi][3])
                    : "r"(aSt[mi] + aOffK[ks]));
            }
#pragma unroll
            for (int mi = 0; mi < 4; mi++)
#pragma unroll
                for (int ni = 0; ni < 4; ni++) {
                    asm volatile(
                        "mma.sync.aligned.m16n8k16.row.col.f32.f16.f16.f32 "
                        "{%0,%1,%2,%3}, {%4,%5,%6,%7}, {%8,%9}, {%0,%1,%2,%3};"
                        : "+f"(acc[mi][ni][0]), "+f"(acc[mi][ni][1]),
                          "+f"(acc[mi][ni][2]), "+f"(acc[mi][ni][3])
                        : "r"(af[mi][0]), "r"(af[mi][1]),
                          "r"(af[mi][2]), "r"(af[mi][3]),
                          "r"(bf[ni][0]), "r"(bf[ni][1]));
                }
        }

        sc = (sc == 2) ? 0 : sc + 1;
        sl = (sl == 2) ? 0 : sl + 1;
    }
    asm volatile("cp.async.wait_group 0;" ::: "memory");

    // ---- epilogue (fragment: c0,c1 = row g; c2,c3 = row g+8; cols 2tg,2tg+1)
#pragma unroll
    for (int mi = 0; mi < 4; mi++) {
#pragma unroll
        for (int ni = 0; ni < 4; ni++) {
            const int n0 = bn + warpN * 32 + ni * 8 + 2 * tg;
#pragma unroll
            for (int h = 0; h < 2; h++) {
                const int m = bm + warpM * 64 + mi * 16 + g + h * 8;
                float t0 = acc[mi][ni][2 * h];
                float t1 = acc[mi][ni][2 * h + 1];
                const size_t idx = (size_t)m * kD + n0;
                if (EPI == EPI_SIGMOID) {
                    t0 = 1.f / (1.f + expf(-t0));
                    t1 = 1.f / (1.f + expf(-t1));
                } else if (EPI == EPI_EWK) {
                    float2 kk = *(const float2*)(aux + idx);
                    t0 = expf(kk.x - expf(t0));
                    t1 = expf(kk.y - expf(t1));
                }
                float2 o = {t0, t1};
                *(float2*)(C + idx) = o;
            }
        }
    }
}

// ---------------------------------------------------------------- blocked scan
__global__ void scan_phase1(const float* __restrict__ ewk,
                            const float* __restrict__ v,
                            const float* __restrict__ td,
                            float* __restrict__ carry)
{
    const int idx = blockIdx.x * blockDim.x + threadIdx.x;  // B*NCH*D
    const int d  = idx & (kD - 1);
    const int ch = (idx >> 11) & (NCH - 1);
    const int b  = idx >> 17;
    const float decay = expf(td[d]);

    float num = 0.f, den = 0.f;
    const size_t base = ((size_t)b * kS + (size_t)ch * LCH) * kD + d;
#pragma unroll 4
    for (int s = 0; s < LCH; s++) {
        const size_t i = base + (size_t)s * kD;
        const float e = ewk[i];
        const float vv = v[i];
        num = decay * num + e * vv;
        den = decay * den + e;
    }
    const size_t ci = (((size_t)b * NCH + ch) * 2) * kD + d;
    carry[ci] = num;
    carry[ci + kD] = den;
}

__global__ void scan_phase2(const float* __restrict__ td,
                            float* __restrict__ carry,
                            float* __restrict__ state_out)
{
    const int idx = blockIdx.x * blockDim.x + threadIdx.x;  // B*D
    const int d = idx & (kD - 1);
    const int b = idx >> 11;
    const float dl = expf(td[d] * (float)LCH);   // decay^LCH

    float num = 0.f, den = 0.f;
    for (int ch = 0; ch < NCH; ch++) {
        const size_t i0 = (((size_t)b * NCH + ch) * 2) * kD + d;
        const float cn = carry[i0];
        const float cd = carry[i0 + kD];
        carry[i0] = num;          // exclusive prefix (state before chunk)
        carry[i0 + kD] = den;
        num = dl * num + cn;
        den = dl * den + cd;
    }
    state_out[(size_t)b * 2 * kD + d] = num;
    state_out[(size_t)b * 2 * kD + kD + d] = den;
}

__global__ void scan_phase3(const float* __restrict__ ewk,
                            const float* __restrict__ v,
                            const float* __restrict__ r,
                            const float* __restrict__ td,
                            const float* __restrict__ carry,
                            __half* __restrict__ y)
{
    const int idx = blockIdx.x * blockDim.x + threadIdx.x;  // B*NCH*D
    const int d  = idx & (kD - 1);
    const int ch = (idx >> 11) & (NCH - 1);
    const int b  = idx >> 17;
    const float decay = expf(td[d]);

    const size_t ci = (((size_t)b * NCH + ch) * 2) * kD + d;
    float num = carry[ci];
    float den = carry[ci + kD];

    const size_t base = ((size_t)b * kS + (size_t)ch * LCH) * kD + d;
#pragma unroll 4
    for (int s = 0; s < LCH; s++) {
        const size_t i = base + (size_t)s * kD;
        const float e = ewk[i];
        const float vv = v[i];
        const float rr = r[i];
        num = decay * num + e * vv;
        den = decay * den + e;
        y[i] = __float2half_rn(rr * (num / (den + 1e-8f)));
    }
}

// ---------------------------------------------------------------- launch
extern "C" void kernel_launch(void* const* d_in, const int* in_sizes, int n_in,
                              void* d_out, int out_size)
{
    const float* x  = (const float*)d_in[0];
    const float* Wr = (const float*)d_in[1];
    const float* Ww = (const float*)d_in[2];
    const float* Wk = (const float*)d_in[3];
    const float* Wv = (const float*)d_in[4];
    const float* Wo = (const float*)d_in[5];
    const float* td = (const float*)d_in[6];
    float* out = (float*)d_out;

    float *bk, *be, *br, *bv, *bcar;
    __half *bxh, *bwh, *byh;
    cudaGetSymbolAddress((void**)&bk,  g_k);
    cudaGetSymbolAddress((void**)&be,  g_e);
    cudaGetSymbolAddress((void**)&br,  g_r);
    cudaGetSymbolAddress((void**)&bv,  g_v);
    cudaGetSymbolAddress((void**)&bxh, g_xh);
    cudaGetSymbolAddress((void**)&bwh, g_wh);
    cudaGetSymbolAddress((void**)&byh, g_yh);
    cudaGetSymbolAddress((void**)&bcar, g_carry);

    __half* wR = bwh + 0 * (size_t)kD * kD;
    __half* wW = bwh + 1 * (size_t)kD * kD;
    __half* wK = bwh + 2 * (size_t)kD * kD;
    __half* wV = bwh + 3 * (size_t)kD * kD;
    __half* wO = bwh + 4 * (size_t)kD * kD;

    cudaFuncSetAttribute(mma_gemm<EPI_NONE>,
                         cudaFuncAttributeMaxDynamicSharedMemorySize, SMEM_BYTES);
    cudaFuncSetAttribute(mma_gemm<EPI_SIGMOID>,
                         cudaFuncAttributeMaxDynamicSharedMemorySize, SMEM_BYTES);
    cudaFuncSetAttribute(mma_gemm<EPI_EWK>,
                         cudaFuncAttributeMaxDynamicSharedMemorySize, SMEM_BYTES);

    const int nx4 = (kM / 4) * kD;
    const int nw4 = (kD / 4) * kD;
    f2h_kernel<<<nx4 / 256, 256>>>(x, bxh, nx4);
    dim3 wg(nw4 / 256, 5);
    f2h_weights<<<wg, 256>>>(Wr, Ww, Wk, Wv, Wo, bwh, nw4);

    dim3 gg(kD / TN, kM / TM);    // (16, 128)

    // launches 2..5 (index 5 = v GEMM -> ncu window)
    mma_gemm<EPI_NONE><<<gg, 256, SMEM_BYTES>>>(bxh, wK, bk, nullptr, kD);
    mma_gemm<EPI_EWK><<<gg, 256, SMEM_BYTES>>>(bxh, wW, be, bk, kD);
    mma_gemm<EPI_SIGMOID><<<gg, 256, SMEM_BYTES>>>(bxh, wR, br, nullptr, kD);
    mma_gemm<EPI_NONE><<<gg, 256, SMEM_BYTES>>>(bxh, wV, bv, nullptr, kD);

    // Blocked WKV scan; final state at d_out tail, y in fp16.
    scan_phase1<<<(kB * NCH * kD) / 256, 256>>>(be, bv, td, bcar);
    scan_phase2<<<(kB * kD) / 256, 256>>>(td, bcar, out + (size_t)kM * kD);
    scan_phase3<<<(kB * NCH * kD) / 256, 256>>>(be, bv, br, td, bcar, byh);

    // out = y @ Wo^T
    mma_gemm<EPI_NONE><<<gg, 256, SMEM_BYTES>>>(byh, wO, out, nullptr, kD);
}

// round 11
// speedup vs baseline: 8.5301x; 1.0205x over previous
#include <cuda_runtime.h>
#include <cuda_fp16.h>
#include <math.h>
#include <stdint.h>

// Problem dims
constexpr int kB = 4;
constexpr int kS = 4096;
constexpr int kD = 2048;
constexpr int kM = kB * kS;          // 16384 rows

// GEMM tiling: 128x128x64 CTA tile (fp16), 8 warps (2 M x 4 N), warp 64x32
constexpr int TM = 128;
constexpr int TN = 128;
constexpr int TK = 64;                              // 64 halves = 128 B rows
constexpr int STAGE_BYTES = (TM + TN) * 128;        // 32 KB
constexpr int STAGES = 3;
constexpr int SMEM_BYTES = STAGES * STAGE_BYTES;    // 96 KB

// Scan blocking
constexpr int NCH = 64;
constexpr int LCH = kS / NCH;        // 64

// Scratch (device globals: allocation-free rule)
__device__ float  g_k[(size_t)kM * kD];       // k (fp32, aux for ewk)
__device__ float  g_e[(size_t)kM * kD];       // ewk
__device__ float  g_r[(size_t)kM * kD];       // r
__device__ float  g_v[(size_t)kM * kD];       // v
__device__ __half g_xh[(size_t)kM * kD];      // x in fp16
__device__ __half g_wh[5][(size_t)kD * kD];   // weights in fp16
__device__ __half g_yh[(size_t)kM * kD];      // y in fp16
__device__ float  g_carry[(size_t)kB * NCH * 2 * kD];

enum { EPI_NONE = 0, EPI_SIGMOID = 1, EPI_EWK = 2 };

// ---------------------------------------------------------------- helpers
__device__ __forceinline__ uint32_t smem_u32(const void* p) {
    return (uint32_t)__cvta_generic_to_shared(p);
}

// ---------------------------------------------------------------- f32 -> f16
__global__ void f2h_kernel(const float* __restrict__ in,
                           __half* __restrict__ out, int n4) {
    int i = blockIdx.x * blockDim.x + threadIdx.x;
    if (i < n4) {
        float4 v = ((const float4*)in)[i];
        ((__half2*)out)[2 * i]     = __floats2half2_rn(v.x, v.y);
        ((__half2*)out)[2 * i + 1] = __floats2half2_rn(v.z, v.w);
    }
}

__global__ void f2h_weights(const float* __restrict__ w0,
                            const float* __restrict__ w1,
                            const float* __restrict__ w2,
                            const float* __restrict__ w3,
                            const float* __restrict__ w4,
                            __half* __restrict__ out, int n4) {
    const float* in;
    switch (blockIdx.y) {
        case 0: in = w0; break;
        case 1: in = w1; break;
        case 2: in = w2; break;
        case 3: in = w3; break;
        default: in = w4; break;
    }
    __half* o = out + (size_t)blockIdx.y * kD * kD;
    int i = blockIdx.x * blockDim.x + threadIdx.x;
    if (i < n4) {
        float4 v = ((const float4*)in)[i];
        ((__half2*)o)[2 * i]     = __floats2half2_rn(v.x, v.y);
        ((__half2*)o)[2 * i + 1] = __floats2half2_rn(v.z, v.w);
    }
}

// ---------------------------------------------------------------- fp16 GEMM
// C[M,N] = A[M,K] @ W[N,K]^T, fp16 operands, fp32 accumulate.
// 3-stage cp.async pipeline, one __syncthreads per chunk, ldmatrix.x4,
// explicit fragment double-buffering across k16-steps (LDSM of ks+1
// issued before the HMMAs of ks).
template <int EPI>
__global__ void __launch_bounds__(256, 2)
mma_gemm(const __half* __restrict__ A, const __half* __restrict__ Wt,
         float* __restrict__ C, const float* __restrict__ aux, int Kk)
{
    extern __shared__ char smem[];
    const uint32_t smem0 = smem_u32(smem);

    const int tid = threadIdx.x;
    const int wid = tid >> 5;
    const int lane = tid & 31;
    const int g = lane >> 2;          // 0..7
    const int tg = lane & 3;          // 0..3
    const int warpM = wid >> 2;       // 0..1
    const int warpN = wid & 3;        // 0..3
    const int bm = blockIdx.y * TM;
    const int bn = blockIdx.x * TN;

    float acc[4][4][4];
#pragma unroll
    for (int a = 0; a < 4; a++)
#pragma unroll
        for (int b = 0; b < 4; b++)
#pragma unroll
            for (int c = 0; c < 4; c++) acc[a][b][c] = 0.f;

    const int nchunk = Kk / TK;       // 32

    // ---- ldmatrix address constants (swizzle XOR = lane&7 everywhere)
    const int arow_l = ((lane >> 3) & 1) * 8 + (lane & 7);
    const int akh    = (lane >> 4) & 1;
    const int brow_l = ((lane >> 4) & 1) * 8 + (lane & 7);
    const int bkh    = (lane >> 3) & 1;
    const uint32_t sw = (uint32_t)(lane & 7);

    uint32_t aBase[4];
#pragma unroll
    for (int mi = 0; mi < 4; mi++)
        aBase[mi] = (uint32_t)(warpM * 64 + mi * 16 + arow_l) * 128;
    uint32_t bBase[2];
#pragma unroll
    for (int p = 0; p < 2; p++)
        bBase[p] = (uint32_t)(TM * 128) +
                   (uint32_t)(warpN * 32 + p * 16 + brow_l) * 128;

    uint32_t aOffK[4];
#pragma unroll
    for (int ks = 0; ks < 4; ks++)
        aOffK[ks] = (((uint32_t)(2 * ks + akh)) ^ sw) << 4;
    // bOff differs from aOff only in bit0 of the chunk index
    const uint32_t abXor = ((uint32_t)(akh ^ bkh)) << 4;

    // ---- loader constants
    const int r0 = tid >> 3;
    const int cc = tid & 7;
    const uint32_t lsw = ((uint32_t)(cc ^ (r0 & 7))) << 4;
    const __half* gA0 = A + (size_t)(bm + r0) * Kk + cc * 8;
    const __half* gB0 = Wt + (size_t)(bn + r0) * Kk + cc * 8;
    const uint32_t spA0 = smem0 + (uint32_t)r0 * 128 + lsw;
    const uint32_t spB0 = spA0 + (uint32_t)(TM * 128);
    const size_t rowStride32 = (size_t)32 * Kk;

    auto load_stage = [&](int s, int c) {
        const uint32_t so = (uint32_t)s * STAGE_BYTES;
        const __half* gA = gA0 + (size_t)c * TK;
        const __half* gB = gB0 + (size_t)c * TK;
#pragma unroll
        for (int it = 0; it < 4; it++) {
            asm volatile("cp.async.cg.shared.global [%0], [%1], 16;"
                         :: "r"(spA0 + so + it * 32 * 128),
                            "l"(gA + it * rowStride32));
        }
#pragma unroll
        for (int it = 0; it < 4; it++) {
            asm volatile("cp.async.cg.shared.global [%0], [%1], 16;"
                         :: "r"(spB0 + so + it * 32 * 128),
                            "l"(gB + it * rowStride32));
        }
    };

    load_stage(0, 0);
    asm volatile("cp.async.commit_group;" ::: "memory");
    load_stage(1, 1);
    asm volatile("cp.async.commit_group;" ::: "memory");

    int sc = 0;                       // compute stage
    int sl = 2;                       // load slot

    // Double-buffered fragments
    uint32_t af[2][4][4];
    uint32_t bf[2][4][2];

    auto ldsm_all = [&](uint32_t st, int ks, int buf) {
        const uint32_t ao = aOffK[ks];
        const uint32_t bo = ao ^ abXor;
#pragma unroll
        for (int p = 0; p < 2; p++) {
            asm volatile(
                "ldmatrix.sync.aligned.m8n8.x4.shared.b16 {%0,%1,%2,%3}, [%4];"
                : "=r"(bf[buf][2 * p][0]), "=r"(bf[buf][2 * p][1]),
                  "=r"(bf[buf][2 * p + 1][0]), "=r"(bf[buf][2 * p + 1][1])
                : "r"(st + bBase[p] + bo));
        }
#pragma unroll
        for (int mi = 0; mi < 4; mi++) {
            asm volatile(
                "ldmatrix.sync.aligned.m8n8.x4.shared.b16 {%0,%1,%2,%3}, [%4];"
                : "=r"(af[buf][mi][0]), "=r"(af[buf][mi][1]),
                  "=r"(af[buf][mi][2]), "=r"(af[buf][mi][3])
                : "r"(st + aBase[mi] + ao));
        }
    };

    auto hmma_all = [&](int buf) {
#pragma unroll
        for (int mi = 0; mi < 4; mi++)
#pragma unroll
            for (int ni = 0; ni < 4; ni++) {
                asm volatile(
                    "mma.sync.aligned.m16n8k16.row.col.f32.f16.f16.f32 "
                    "{%0,%1,%2,%3}, {%4,%5,%6,%7}, {%8,%9}, {%0,%1,%2,%3};"
                    : "+f"(acc[mi][ni][0]), "+f"(acc[mi][ni][1]),
                      "+f"(acc[mi][ni][2]), "+f"(acc[mi][ni][3])
                    : "r"(af[buf][mi][0]), "r"(af[buf][mi][1]),
                      "r"(af[buf][mi][2]), "r"(af[buf][mi][3]),
                      "r"(bf[buf][ni][0]), "r"(bf[buf][ni][1]));
            }
    };

    for (int c = 0; c < nchunk; c++) {
        asm volatile("cp.async.wait_group 1;" ::: "memory");
        __syncthreads();

        const uint32_t st = smem0 + (uint32_t)sc * STAGE_BYTES;

        // First LDSM batch of the chunk, then kick the DMA refill
        ldsm_all(st, 0, 0);
        if (c + 2 < nchunk) load_stage(sl, c + 2);
        asm volatile("cp.async.commit_group;" ::: "memory");

#pragma unroll
        for (int ks = 0; ks < 4; ks++) {
            const int cur = ks & 1;
            if (ks < 3) ldsm_all(st, ks + 1, cur ^ 1);
            hmma_all(cur);
        }

        sc = (sc == 2) ? 0 : sc + 1;
        sl = (sl == 2) ? 0 : sl + 1;
    }
    asm volatile("cp.async.wait_group 0;" ::: "memory");

    // ---- epilogue (fragment: c0,c1 = row g; c2,c3 = row g+8; cols 2tg,2tg+1)
#pragma unroll
    for (int mi = 0; mi < 4; mi++) {
#pragma unroll
        for (int ni = 0; ni < 4; ni++) {
            const int n0 = bn + warpN * 32 + ni * 8 + 2 * tg;
#pragma unroll
            for (int h = 0; h < 2; h++) {
                const int m = bm + warpM * 64 + mi * 16 + g + h * 8;
                float t0 = acc[mi][ni][2 * h];
                float t1 = acc[mi][ni][2 * h + 1];
                const size_t idx = (size_t)m * kD + n0;
                if (EPI == EPI_SIGMOID) {
                    t0 = 1.f / (1.f + expf(-t0));
                    t1 = 1.f / (1.f + expf(-t1));
                } else if (EPI == EPI_EWK) {
                    float2 kk = *(const float2*)(aux + idx);
                    t0 = expf(kk.x - expf(t0));
                    t1 = expf(kk.y - expf(t1));
                }
                float2 o = {t0, t1};
                *(float2*)(C + idx) = o;
            }
        }
    }
}

// ---------------------------------------------------------------- blocked scan
__global__ void scan_phase1(const float* __restrict__ ewk,
                            const float* __restrict__ v,
                            const float* __restrict__ td,
                            float* __restrict__ carry)
{
    const int idx = blockIdx.x * blockDim.x + threadIdx.x;  // B*NCH*D
    const int d  = idx & (kD - 1);
    const int ch = (idx >> 11) & (NCH - 1);
    const int b  = idx >> 17;
    const float decay = expf(td[d]);

    float num = 0.f, den = 0.f;
    const size_t base = ((size_t)b * kS + (size_t)ch * LCH) * kD + d;
#pragma unroll 4
    for (int s = 0; s < LCH; s++) {
        const size_t i = base + (size_t)s * kD;
        const float e = ewk[i];
        const float vv = v[i];
        num = decay * num + e * vv;
        den = decay * den + e;
    }
    const size_t ci = (((size_t)b * NCH + ch) * 2) * kD + d;
    carry[ci] = num;
    carry[ci + kD] = den;
}

__global__ void scan_phase2(const float* __restrict__ td,
                            float* __restrict__ carry,
                            float* __restrict__ state_out)
{
    const int idx = blockIdx.x * blockDim.x + threadIdx.x;  // B*D
    const int d = idx & (kD - 1);
    const int b = idx >> 11;
    const float dl = expf(td[d] * (float)LCH);   // decay^LCH

    float num = 0.f, den = 0.f;
    for (int ch = 0; ch < NCH; ch++) {
        const size_t i0 = (((size_t)b * NCH + ch) * 2) * kD + d;
        const float cn = carry[i0];
        const float cd = carry[i0 + kD];
        carry[i0] = num;          // exclusive prefix (state before chunk)
        carry[i0 + kD] = den;
        num = dl * num + cn;
        den = dl * den + cd;
    }
    state_out[(size_t)b * 2 * kD + d] = num;
    state_out[(size_t)b * 2 * kD + kD + d] = den;
}

__global__ void scan_phase3(const float* __restrict__ ewk,
                            const float* __restrict__ v,
                            const float* __restrict__ r,
                            const float* __restrict__ td,
                            const float* __restrict__ carry,
                            __half* __restrict__ y)
{
    const int idx = blockIdx.x * blockDim.x + threadIdx.x;  // B*NCH*D
    const int d  = idx & (kD - 1);
    const int ch = (idx >> 11) & (NCH - 1);
    const int b  = idx >> 17;
    const float decay = expf(td[d]);

    const size_t ci = (((size_t)b * NCH + ch) * 2) * kD + d;
    float num = carry[ci];
    float den = carry[ci + kD];

    const size_t base = ((size_t)b * kS + (size_t)ch * LCH) * kD + d;
#pragma unroll 4
    for (int s = 0; s < LCH; s++) {
        const size_t i = base + (size_t)s * kD;
        const float e = ewk[i];
        const float vv = v[i];
        const float rr = r[i];
        num = decay * num + e * vv;
        den = decay * den + e;
        y[i] = __float2half_rn(rr * (num / (den + 1e-8f)));
    }
}

// ---------------------------------------------------------------- launch
extern "C" void kernel_launch(void* const* d_in, const int* in_sizes, int n_in,
                              void* d_out, int out_size)
{
    const float* x  = (const float*)d_in[0];
    const float* Wr = (const float*)d_in[1];
    const float* Ww = (const float*)d_in[2];
    const float* Wk = (const float*)d_in[3];
    const float* Wv = (const float*)d_in[4];
    const float* Wo = (const float*)d_in[5];
    const float* td = (const float*)d_in[6];
    float* out = (float*)d_out;

    float *bk, *be, *br, *bv, *bcar;
    __half *bxh, *bwh, *byh;
    cudaGetSymbolAddress((void**)&bk,  g_k);
    cudaGetSymbolAddress((void**)&be,  g_e);
    cudaGetSymbolAddress((void**)&br,  g_r);
    cudaGetSymbolAddress((void**)&bv,  g_v);
    cudaGetSymbolAddress((void**)&bxh, g_xh);
    cudaGetSymbolAddress((void**)&bwh, g_wh);
    cudaGetSymbolAddress((void**)&byh, g_yh);
    cudaGetSymbolAddress((void**)&bcar, g_carry);

    __half* wR = bwh + 0 * (size_t)kD * kD;
    __half* wW = bwh + 1 * (size_t)kD * kD;
    __half* wK = bwh + 2 * (size_t)kD * kD;
    __half* wV = bwh + 3 * (size_t)kD * kD;
    __half* wO = bwh + 4 * (size_t)kD * kD;

    cudaFuncSetAttribute(mma_gemm<EPI_NONE>,
                         cudaFuncAttributeMaxDynamicSharedMemorySize, SMEM_BYTES);
    cudaFuncSetAttribute(mma_gemm<EPI_SIGMOID>,
                         cudaFuncAttributeMaxDynamicSharedMemorySize, SMEM_BYTES);
    cudaFuncSetAttribute(mma_gemm<EPI_EWK>,
                         cudaFuncAttributeMaxDynamicSharedMemorySize, SMEM_BYTES);

    const int nx4 = (kM / 4) * kD;
    const int nw4 = (kD / 4) * kD;
    f2h_kernel<<<nx4 / 256, 256>>>(x, bxh, nx4);
    dim3 wg(nw4 / 256, 5);
    f2h_weights<<<wg, 256>>>(Wr, Ww, Wk, Wv, Wo, bwh, nw4);

    dim3 gg(kD / TN, kM / TM);    // (16, 128)

    // launches 2..5 (index 5 = v GEMM -> ncu window)
    mma_gemm<EPI_NONE><<<gg, 256, SMEM_BYTES>>>(bxh, wK, bk, nullptr, kD);
    mma_gemm<EPI_EWK><<<gg, 256, SMEM_BYTES>>>(bxh, wW, be, bk, kD);
    mma_gemm<EPI_SIGMOID><<<gg, 256, SMEM_BYTES>>>(bxh, wR, br, nullptr, kD);
    mma_gemm<EPI_NONE><<<gg, 256, SMEM_BYTES>>>(bxh, wV, bv, nullptr, kD);

    // Blocked WKV scan; final state at d_out tail, y in fp16.
    scan_phase1<<<(kB * NCH * kD) / 256, 256>>>(be, bv, td, bcar);
    scan_phase2<<<(kB * kD) / 256, 256>>>(td, bcar, out + (size_t)kM * kD);
    scan_phase3<<<(kB * NCH * kD) / 256, 256>>>(be, bv, br, td, bcar, byh);

    // out = y @ Wo^T
    mma_gemm<EPI_NONE><<<gg, 256, SMEM_BYTES>>>(byh, wO, out, nullptr, kD);
}

// round 13
// speedup vs baseline: 8.6893x; 1.0187x over previous
#include <cuda_runtime.h>
#include <cuda_fp16.h>
#include <math.h>
#include <stdint.h>

// Problem dims
constexpr int kB = 4;
constexpr int kS = 4096;
constexpr int kD = 2048;
constexpr int kM = kB * kS;          // 16384 rows

// GEMM tiling: 128x128x64 CTA tile, 4 warps (2 M x 2 N), warp tile 64x64
constexpr int TM = 128;
constexpr int TN = 128;
constexpr int TK = 64;                              // 64 halves = 128 B rows
constexpr int STAGE_BYTES = (TM + TN) * 128;        // 32 KB
constexpr int STAGES = 3;
constexpr int SMEM_BYTES = STAGES * STAGE_BYTES;    // 96 KB

// Scan blocking
constexpr int NCH = 64;
constexpr int LCH = kS / NCH;        // 64

// Scratch (device globals: allocation-free rule)
__device__ float  g_k[(size_t)kM * kD];       // k (fp32, aux for ewk)
__device__ float  g_e[(size_t)kM * kD];       // ewk
__device__ float  g_r[(size_t)kM * kD];       // r
__device__ float  g_v[(size_t)kM * kD];       // v
__device__ __half g_xh[(size_t)kM * kD];      // x in fp16
__device__ __half g_wh[5][(size_t)kD * kD];   // weights in fp16
__device__ __half g_yh[(size_t)kM * kD];      // y in fp16
__device__ float  g_carry[(size_t)kB * NCH * 2 * kD];

enum { EPI_NONE = 0, EPI_SIGMOID = 1, EPI_EWK = 2 };

// ---------------------------------------------------------------- helpers
__device__ __forceinline__ uint32_t smem_u32(const void* p) {
    return (uint32_t)__cvta_generic_to_shared(p);
}

// ---------------------------------------------------------------- f32 -> f16
__global__ void f2h_kernel(const float* __restrict__ in,
                           __half* __restrict__ out, int n4) {
    int i = blockIdx.x * blockDim.x + threadIdx.x;
    if (i < n4) {
        float4 v = ((const float4*)in)[i];
        ((__half2*)out)[2 * i]     = __floats2half2_rn(v.x, v.y);
        ((__half2*)out)[2 * i + 1] = __floats2half2_rn(v.z, v.w);
    }
}

__global__ void f2h_weights(const float* __restrict__ w0,
                            const float* __restrict__ w1,
                            const float* __restrict__ w2,
                            const float* __restrict__ w3,
                            const float* __restrict__ w4,
                            __half* __restrict__ out, int n4) {
    const float* in;
    switch (blockIdx.y) {
        case 0: in = w0; break;
        case 1: in = w1; break;
        case 2: in = w2; break;
        case 3: in = w3; break;
        default: in = w4; break;
    }
    __half* o = out + (size_t)blockIdx.y * kD * kD;
    int i = blockIdx.x * blockDim.x + threadIdx.x;
    if (i < n4) {
        float4 v = ((const float4*)in)[i];
        ((__half2*)o)[2 * i]     = __floats2half2_rn(v.x, v.y);
        ((__half2*)o)[2 * i + 1] = __floats2half2_rn(v.z, v.w);
    }
}

// ---------------------------------------------------------------- fp16 GEMM
// C[M,N] = A[M,K] @ W[N,K]^T, fp16 operands, fp32 accumulate.
// 4 warps, 64x64 warp tiles (2x better A-reuse, 1.54x FLOP/smem-byte).
// 3-stage cp.async pipeline, one __syncthreads per chunk, ldmatrix.x4.
template <int EPI>
__global__ void __launch_bounds__(128, 2)
mma_gemm(const __half* __restrict__ A, const __half* __restrict__ Wt,
         float* __restrict__ C, const float* __restrict__ aux, int Kk)
{
    extern __shared__ char smem[];
    const uint32_t smem0 = smem_u32(smem);

    const int tid = threadIdx.x;
    const int wid = tid >> 5;
    const int lane = tid & 31;
    const int g = lane >> 2;          // 0..7
    const int tg = lane & 3;          // 0..3
    const int warpM = wid >> 1;       // 0..1
    const int warpN = wid & 1;        // 0..1
    const int bm = blockIdx.y * TM;
    const int bn = blockIdx.x * TN;

    float acc[4][8][4];
#pragma unroll
    for (int a = 0; a < 4; a++)
#pragma unroll
        for (int b = 0; b < 8; b++)
#pragma unroll
            for (int c = 0; c < 4; c++) acc[a][b][c] = 0.f;

    const int nchunk = Kk / TK;       // 32

    // ---- ldmatrix address constants (fragment row & 7 == lane & 7 always)
    const int arow_l = ((lane >> 3) & 1) * 8 + (lane & 7);
    const int akh    = (lane >> 4) & 1;
    const int brow_l = ((lane >> 4) & 1) * 8 + (lane & 7);
    const int bkh    = (lane >> 3) & 1;
    const uint32_t sw = (uint32_t)(lane & 7);

    uint32_t aBase[4];
#pragma unroll
    for (int mi = 0; mi < 4; mi++)
        aBase[mi] = (uint32_t)(warpM * 64 + mi * 16 + arow_l) * 128;
    uint32_t bBase[4];
#pragma unroll
    for (int p = 0; p < 4; p++)
        bBase[p] = (uint32_t)(TM * 128) +
                   (uint32_t)(warpN * 64 + p * 16 + brow_l) * 128;

    uint32_t aOffK[4];
#pragma unroll
    for (int ks = 0; ks < 4; ks++)
        aOffK[ks] = (((uint32_t)(2 * ks + akh)) ^ sw) << 4;
    const uint32_t abXor = ((uint32_t)(akh ^ bkh)) << 4;

    // ---- loader constants: 128 threads, 16 x 16B chunks each per stage.
    // i = tid + 128*it -> row = (tid>>3) + 16*it, cc = tid&7.
    const int r0 = tid >> 3;          // 0..15
    const int cc = tid & 7;
    const uint32_t lsw = ((uint32_t)(cc ^ (r0 & 7))) << 4;
    const __half* gA0 = A + (size_t)(bm + r0) * Kk + cc * 8;
    const __half* gB0 = Wt + (size_t)(bn + r0) * Kk + cc * 8;
    const uint32_t spA0 = smem0 + (uint32_t)r0 * 128 + lsw;
    const uint32_t spB0 = spA0 + (uint32_t)(TM * 128);
    const size_t rowStride16 = (size_t)16 * Kk;

    auto load_stage = [&](int s, int c) {
        const uint32_t so = (uint32_t)s * STAGE_BYTES;
        const __half* gA = gA0 + (size_t)c * TK;
        const __half* gB = gB0 + (size_t)c * TK;
#pragma unroll
        for (int it = 0; it < 8; it++) {
            asm volatile("cp.async.cg.shared.global [%0], [%1], 16;"
                         :: "r"(spA0 + so + it * 16 * 128),
                            "l"(gA + it * rowStride16));
        }
#pragma unroll
        for (int it = 0; it < 8; it++) {
            asm volatile("cp.async.cg.shared.global [%0], [%1], 16;"
                         :: "r"(spB0 + so + it * 16 * 128),
                            "l"(gB + it * rowStride16));
        }
    };

    load_stage(0, 0);
    asm volatile("cp.async.commit_group;" ::: "memory");
    load_stage(1, 1);
    asm volatile("cp.async.commit_group;" ::: "memory");

    int sc = 0;                       // compute stage
    int sl = 2;                       // load slot

    for (int c = 0; c < nchunk; c++) {
        asm volatile("cp.async.wait_group 1;" ::: "memory");
        __syncthreads();

        const uint32_t st = smem0 + (uint32_t)sc * STAGE_BYTES;

        // Kick the DMA refill, then compute the chunk
        if (c + 2 < nchunk) load_stage(sl, c + 2);
        asm volatile("cp.async.commit_group;" ::: "memory");

#pragma unroll
        for (int ks = 0; ks < 4; ks++) {
            const uint32_t ao = aOffK[ks];
            const uint32_t bo = ao ^ abXor;
            uint32_t af[4][4];
            uint32_t bf[8][2];
#pragma unroll
            for (int p = 0; p < 4; p++) {
                asm volatile(
                    "ldmatrix.sync.aligned.m8n8.x4.shared.b16 "
                    "{%0,%1,%2,%3}, [%4];"
                    : "=r"(bf[2 * p][0]), "=r"(bf[2 * p][1]),
                      "=r"(bf[2 * p + 1][0]), "=r"(bf[2 * p + 1][1])
                    : "r"(st + bBase[p] + bo));
            }
#pragma unroll
            for (int mi = 0; mi < 4; mi++) {
                asm volatile(
                    "ldmatrix.sync.aligned.m8n8.x4.shared.b16 "
                    "{%0,%1,%2,%3}, [%4];"
                    : "=r"(af[mi][0]), "=r"(af[mi][1]),
                      "=r"(af[mi][2]), "=r"(af[mi][3])
                    : "r"(st + aBase[mi] + ao));
            }
#pragma unroll
            for (int mi = 0; mi < 4; mi++)
#pragma unroll
                for (int ni = 0; ni < 8; ni++) {
                    asm volatile(
                        "mma.sync.aligned.m16n8k16.row.col.f32.f16.f16.f32 "
                        "{%0,%1,%2,%3}, {%4,%5,%6,%7}, {%8,%9}, {%0,%1,%2,%3};"
                        : "+f"(acc[mi][ni][0]), "+f"(acc[mi][ni][1]),
                          "+f"(acc[mi][ni][2]), "+f"(acc[mi][ni][3])
                        : "r"(af[mi][0]), "r"(af[mi][1]),
                          "r"(af[mi][2]), "r"(af[mi][3]),
                          "r"(bf[ni][0]), "r"(bf[ni][1]));
                }
        }

        sc = (sc == 2) ? 0 : sc + 1;
        sl = (sl == 2) ? 0 : sl + 1;
    }
    asm volatile("cp.async.wait_group 0;" ::: "memory");

    // ---- epilogue (fragment: c0,c1 = row g; c2,c3 = row g+8; cols 2tg,2tg+1)
#pragma unroll
    for (int mi = 0; mi < 4; mi++) {
#pragma unroll
        for (int ni = 0; ni < 8; ni++) {
            const int n0 = bn + warpN * 64 + ni * 8 + 2 * tg;
#pragma unroll
            for (int h = 0; h < 2; h++) {
                const int m = bm + warpM * 64 + mi * 16 + g + h * 8;
                float t0 = acc[mi][ni][2 * h];
                float t1 = acc[mi][ni][2 * h + 1];
                const size_t idx = (size_t)m * kD + n0;
                if (EPI == EPI_SIGMOID) {
                    t0 = 1.f / (1.f + expf(-t0));
                    t1 = 1.f / (1.f + expf(-t1));
                } else if (EPI == EPI_EWK) {
                    float2 kk = *(const float2*)(aux + idx);
                    t0 = expf(kk.x - expf(t0));
                    t1 = expf(kk.y - expf(t1));
                }
                float2 o = {t0, t1};
                *(float2*)(C + idx) = o;
            }
        }
    }
}

// ---------------------------------------------------------------- blocked scan
__global__ void scan_phase1(const float* __restrict__ ewk,
                            const float* __restrict__ v,
                            const float* __restrict__ td,
                            float* __restrict__ carry)
{
    const int idx = blockIdx.x * blockDim.x + threadIdx.x;  // B*NCH*D
    const int d  = idx & (kD - 1);
    const int ch = (idx >> 11) & (NCH - 1);
    const int b  = idx >> 17;
    const float decay = expf(td[d]);

    float num = 0.f, den = 0.f;
    const size_t base = ((size_t)b * kS + (size_t)ch * LCH) * kD + d;
#pragma unroll 4
    for (int s = 0; s < LCH; s++) {
        const size_t i = base + (size_t)s * kD;
        const float e = ewk[i];
        const float vv = v[i];
        num = decay * num + e * vv;
        den = decay * den + e;
    }
    const size_t ci = (((size_t)b * NCH + ch) * 2) * kD + d;
    carry[ci] = num;
    carry[ci + kD] = den;
}

__global__ void scan_phase2(const float* __restrict__ td,
                            float* __restrict__ carry,
                            float* __restrict__ state_out)
{
    const int idx = blockIdx.x * blockDim.x + threadIdx.x;  // B*D
    const int d = idx & (kD - 1);
    const int b = idx >> 11;
    const float dl = expf(td[d] * (float)LCH);   // decay^LCH

    float num = 0.f, den = 0.f;
    for (int ch = 0; ch < NCH; ch++) {
        const size_t i0 = (((size_t)b * NCH + ch) * 2) * kD + d;
        const float cn = carry[i0];
        const float cd = carry[i0 + kD];
        carry[i0] = num;          // exclusive prefix (state before chunk)
        carry[i0 + kD] = den;
        num = dl * num + cn;
        den = dl * den + cd;
    }
    state_out[(size_t)b * 2 * kD + d] = num;
    state_out[(size_t)b * 2 * kD + kD + d] = den;
}

__global__ void scan_phase3(const float* __restrict__ ewk,
                            const float* __restrict__ v,
                            const float* __restrict__ r,
                            const float* __restrict__ td,
                            const float* __restrict__ carry,
                            __half* __restrict__ y)
{
    const int idx = blockIdx.x * blockDim.x + threadIdx.x;  // B*NCH*D
    const int d  = idx & (kD - 1);
    const int ch = (idx >> 11) & (NCH - 1);
    const int b  = idx >> 17;
    const float decay = expf(td[d]);

    const size_t ci = (((size_t)b * NCH + ch) * 2) * kD + d;
    float num = carry[ci];
    float den = carry[ci + kD];

    const size_t base = ((size_t)b * kS + (size_t)ch * LCH) * kD + d;
#pragma unroll 4
    for (int s = 0; s < LCH; s++) {
        const size_t i = base + (size_t)s * kD;
        const float e = ewk[i];
        const float vv = v[i];
        const float rr = r[i];
        num = decay * num + e * vv;
        den = decay * den + e;
        y[i] = __float2half_rn(rr * (num / (den + 1e-8f)));
    }
}

// ---------------------------------------------------------------- launch
extern "C" void kernel_launch(void* const* d_in, const int* in_sizes, int n_in,
                              void* d_out, int out_size)
{
    const float* x  = (const float*)d_in[0];
    const float* Wr = (const float*)d_in[1];
    const float* Ww = (const float*)d_in[2];
    const float* Wk = (const float*)d_in[3];
    const float* Wv = (const float*)d_in[4];
    const float* Wo = (const float*)d_in[5];
    const float* td = (const float*)d_in[6];
    float* out = (float*)d_out;

    float *bk, *be, *br, *bv, *bcar;
    __half *bxh, *bwh, *byh;
    cudaGetSymbolAddress((void**)&bk,  g_k);
    cudaGetSymbolAddress((void**)&be,  g_e);
    cudaGetSymbolAddress((void**)&br,  g_r);
    cudaGetSymbolAddress((void**)&bv,  g_v);
    cudaGetSymbolAddress((void**)&bxh, g_xh);
    cudaGetSymbolAddress((void**)&bwh, g_wh);
    cudaGetSymbolAddress((void**)&byh, g_yh);
    cudaGetSymbolAddress((void**)&bcar, g_carry);

    __half* wR = bwh + 0 * (size_t)kD * kD;
    __half* wW = bwh + 1 * (size_t)kD * kD;
    __half* wK = bwh + 2 * (size_t)kD * kD;
    __half* wV = bwh + 3 * (size_t)kD * kD;
    __half* wO = bwh + 4 * (size_t)kD * kD;

    cudaFuncSetAttribute(mma_gemm<EPI_NONE>,
                         cudaFuncAttributeMaxDynamicSharedMemorySize, SMEM_BYTES);
    cudaFuncSetAttribute(mma_gemm<EPI_SIGMOID>,
                         cudaFuncAttributeMaxDynamicSharedMemorySize, SMEM_BYTES);
    cudaFuncSetAttribute(mma_gemm<EPI_EWK>,
                         cudaFuncAttributeMaxDynamicSharedMemorySize, SMEM_BYTES);

    const int nx4 = (kM / 4) * kD;
    const int nw4 = (kD / 4) * kD;
    f2h_kernel<<<nx4 / 256, 256>>>(x, bxh, nx4);
    dim3 wg(nw4 / 256, 5);
    f2h_weights<<<wg, 256>>>(Wr, Ww, Wk, Wv, Wo, bwh, nw4);

    dim3 gg(kD / TN, kM / TM);    // (16, 128)

    // launches 2..5 (index 5 = v GEMM -> ncu window)
    mma_gemm<EPI_NONE><<<gg, 128, SMEM_BYTES>>>(bxh, wK, bk, nullptr, kD);
    mma_gemm<EPI_EWK><<<gg, 128, SMEM_BYTES>>>(bxh, wW, be, bk, kD);
    mma_gemm<EPI_SIGMOID><<<gg, 128, SMEM_BYTES>>>(bxh, wR, br, nullptr, kD);
    mma_gemm<EPI_NONE><<<gg, 128, SMEM_BYTES>>>(bxh, wV, bv, nullptr, kD);

    // Blocked WKV scan; final state at d_out tail, y in fp16.
    scan_phase1<<<(kB * NCH * kD) / 256, 256>>>(be, bv, td, bcar);
    scan_phase2<<<(kB * kD) / 256, 256>>>(td, bcar, out + (size_t)kM * kD);
    scan_phase3<<<(kB * NCH * kD) / 256, 256>>>(be, bv, br, td, bcar, byh);

    // out = y @ Wo^T
    mma_gemm<EPI_NONE><<<gg, 128, SMEM_BYTES>>>(byh, wO, out, nullptr, kD);
}